// round 1
// baseline (speedup 1.0000x reference)
#include <cuda_runtime.h>
#include <cuda_bf16.h>
#include <math.h>

// ---------------- problem dims ----------------
#define BB 256
#define LL 96
#define DD 512
#define HH 8
#define HDIM 64
#define DFF 2048
#define NT (BB*LL)          // 24576 tokens
#define SCALE 0.125f        // HD^-0.5 = 64^-0.5
#define EPS_LN 1e-5f

// ---------------- scratch (no allocs allowed) ----------------
__device__ float g_q [NT*DD];
__device__ float g_k [NT*DD];
__device__ float g_v [NT*DD];
__device__ float g_ao[NT*DD];
__device__ float g_t [NT*DD];
__device__ float g_x [NT*DD];
__device__ float g_ff[NT*DFF];

// ---------------- SGEMM: C = A[M,K] @ W[K,N] + bias (+epilogue) ----------------
// EPI: 0 = bias, 1 = bias + exact gelu, 2 = bias + residual
template<int EPI>
__global__ void __launch_bounds__(256) sgemm_kernel(
    const float* __restrict__ A, const float* __restrict__ W,
    const float* __restrict__ bias, const float* __restrict__ resid,
    float* __restrict__ C, int M, int N, int K)
{
    __shared__ float As[16*128];   // [k][m] transposed
    __shared__ float Bs[16*128];   // [k][n]
    const int bx = blockIdx.x;     // N tile
    const int by = blockIdx.y;     // M tile
    const int tid = threadIdx.x;
    const int tr = tid >> 4;       // 0..15
    const int tc = tid & 15;       // 0..15

    const float* Ablk = A + (size_t)by * 128 * K;
    const float* Wblk = W + (size_t)bx * 128;

    float acc[8][8];
    #pragma unroll
    for (int i = 0; i < 8; i++)
        #pragma unroll
        for (int j = 0; j < 8; j++) acc[i][j] = 0.f;

    for (int k0 = 0; k0 < K; k0 += 16) {
        // A tile: 128 rows x 16 cols -> As[k][m]
        #pragma unroll
        for (int t = 0; t < 2; t++) {
            int f = tid + t * 256;            // 0..511 float4 slots
            int row = f >> 2;                 // 0..127
            int c4  = (f & 3) * 4;            // 0,4,8,12
            float4 va = *reinterpret_cast<const float4*>(Ablk + (size_t)row * K + k0 + c4);
            As[(c4 + 0) * 128 + row] = va.x;
            As[(c4 + 1) * 128 + row] = va.y;
            As[(c4 + 2) * 128 + row] = va.z;
            As[(c4 + 3) * 128 + row] = va.w;
        }
        // W tile: 16 rows x 128 cols -> Bs[k][n]
        #pragma unroll
        for (int t = 0; t < 2; t++) {
            int f = tid + t * 256;
            int row = f >> 5;                 // 0..15
            int c4  = (f & 31) * 4;           // 0..124
            *reinterpret_cast<float4*>(Bs + row * 128 + c4) =
                *reinterpret_cast<const float4*>(Wblk + (size_t)(k0 + row) * N + c4);
        }
        __syncthreads();
        #pragma unroll
        for (int kk = 0; kk < 16; kk++) {
            float ar[8], br[8];
            #pragma unroll
            for (int i = 0; i < 8; i++) ar[i] = As[kk * 128 + tr * 8 + i];
            #pragma unroll
            for (int j = 0; j < 8; j++) br[j] = Bs[kk * 128 + tc * 8 + j];
            #pragma unroll
            for (int i = 0; i < 8; i++)
                #pragma unroll
                for (int j = 0; j < 8; j++)
                    acc[i][j] = fmaf(ar[i], br[j], acc[i][j]);
        }
        __syncthreads();
    }

    #pragma unroll
    for (int i = 0; i < 8; i++) {
        int row = by * 128 + tr * 8 + i;
        #pragma unroll
        for (int j = 0; j < 8; j += 4) {
            int col = bx * 128 + tc * 8 + j;
            float4 bv = *reinterpret_cast<const float4*>(bias + col);
            float4 r;
            r.x = acc[i][j + 0] + bv.x;
            r.y = acc[i][j + 1] + bv.y;
            r.z = acc[i][j + 2] + bv.z;
            r.w = acc[i][j + 3] + bv.w;
            if (EPI == 1) {
                r.x = 0.5f * r.x * (1.f + erff(r.x * 0.70710678118654752f));
                r.y = 0.5f * r.y * (1.f + erff(r.y * 0.70710678118654752f));
                r.z = 0.5f * r.z * (1.f + erff(r.z * 0.70710678118654752f));
                r.w = 0.5f * r.w * (1.f + erff(r.w * 0.70710678118654752f));
            }
            if (EPI == 2) {
                float4 rv = *reinterpret_cast<const float4*>(resid + (size_t)row * N + col);
                r.x += rv.x; r.y += rv.y; r.z += rv.z; r.w += rv.w;
            }
            *reinterpret_cast<float4*>(C + (size_t)row * N + col) = r;
        }
    }
}

// ---------------- fused attention per (b,h) ----------------
#define SQ_LD 65
#define SS_LD 97
#define SMEM_ATTN ((2*LL*SQ_LD + LL*SS_LD + LL*HDIM) * (int)sizeof(float))

__global__ void __launch_bounds__(256) attn_kernel(
    const float* __restrict__ q, const float* __restrict__ k, const float* __restrict__ v,
    const float* __restrict__ matrix, float* __restrict__ scores_out, float* __restrict__ ao)
{
    extern __shared__ float sm[];
    float* qs = sm;                        // [96][65]
    float* ks = qs + LL * SQ_LD;           // [96][65]
    float* ss = ks + LL * SQ_LD;           // [96][97]
    float* vs = ss + LL * SS_LD;           // [96][64]

    const int bh = blockIdx.x;
    const int b = bh / HH, h = bh % HH;
    const int tid = threadIdx.x;
    const size_t base = ((size_t)b * LL) * DD + h * HDIM;

    // load q,k,v tiles (strided rows, coalesced within row)
    for (int idx = tid; idx < LL * HDIM; idx += 256) {
        int l = idx >> 6, d = idx & 63;
        size_t g = base + (size_t)l * DD + d;
        qs[l * SQ_LD + d] = q[g];
        ks[l * SQ_LD + d] = k[g];
        vs[l * HDIM  + d] = v[g];
    }
    __syncthreads();

    const float* mb  = matrix     + (size_t)bh * LL * LL;
    float*       sob = scores_out + (size_t)bh * LL * LL;

    // S = (q k^T) * matrix * SCALE ; register-tiled 6x6 per thread (16x16 threads)
    {
        const int ti = tid >> 4, tj = tid & 15;
        const int i0 = ti * 6, j0 = tj * 6;
        float accS[6][6];
        #pragma unroll
        for (int i = 0; i < 6; i++)
            #pragma unroll
            for (int j = 0; j < 6; j++) accS[i][j] = 0.f;
        #pragma unroll 8
        for (int kk = 0; kk < HDIM; kk++) {
            float ar[6], br[6];
            #pragma unroll
            for (int i = 0; i < 6; i++) ar[i] = qs[(i0 + i) * SQ_LD + kk];
            #pragma unroll
            for (int j = 0; j < 6; j++) br[j] = ks[(j0 + j) * SQ_LD + kk];
            #pragma unroll
            for (int i = 0; i < 6; i++)
                #pragma unroll
                for (int j = 0; j < 6; j++)
                    accS[i][j] = fmaf(ar[i], br[j], accS[i][j]);
        }
        #pragma unroll
        for (int i = 0; i < 6; i++)
            #pragma unroll
            for (int j = 0; j < 6; j++) {
                int idx = (i0 + i) * LL + (j0 + j);
                float s = accS[i][j] * mb[idx] * SCALE;
                sob[idx] = s;
                ss[(i0 + i) * SS_LD + (j0 + j)] = s;
            }
    }
    __syncthreads();

    // softmax rows: warp per row
    {
        const int w = tid >> 5, lane = tid & 31;
        for (int r = w; r < LL; r += 8) {
            float vals[3];
            float m = -1e30f;
            #pragma unroll
            for (int t = 0; t < 3; t++) {
                vals[t] = ss[r * SS_LD + lane + t * 32];
                m = fmaxf(m, vals[t]);
            }
            #pragma unroll
            for (int o = 16; o > 0; o >>= 1) m = fmaxf(m, __shfl_xor_sync(0xffffffffu, m, o));
            float sum = 0.f;
            #pragma unroll
            for (int t = 0; t < 3; t++) { vals[t] = __expf(vals[t] - m); sum += vals[t]; }
            #pragma unroll
            for (int o = 16; o > 0; o >>= 1) sum += __shfl_xor_sync(0xffffffffu, sum, o);
            float inv = 1.f / sum;
            #pragma unroll
            for (int t = 0; t < 3; t++) ss[r * SS_LD + lane + t * 32] = vals[t] * inv;
        }
    }
    __syncthreads();

    // O = P @ V ; 6 rows x 4 cols per thread
    {
        const int ti = tid >> 4, tj = tid & 15;
        const int i0 = ti * 6, d0 = tj * 4;
        float accO[6][4];
        #pragma unroll
        for (int i = 0; i < 6; i++)
            #pragma unroll
            for (int d = 0; d < 4; d++) accO[i][d] = 0.f;
        #pragma unroll 4
        for (int kk = 0; kk < LL; kk++) {
            float4 bv = *reinterpret_cast<const float4*>(vs + kk * HDIM + d0);
            float ar[6];
            #pragma unroll
            for (int i = 0; i < 6; i++) ar[i] = ss[(i0 + i) * SS_LD + kk];
            #pragma unroll
            for (int i = 0; i < 6; i++) {
                accO[i][0] = fmaf(ar[i], bv.x, accO[i][0]);
                accO[i][1] = fmaf(ar[i], bv.y, accO[i][1]);
                accO[i][2] = fmaf(ar[i], bv.z, accO[i][2]);
                accO[i][3] = fmaf(ar[i], bv.w, accO[i][3]);
            }
        }
        #pragma unroll
        for (int i = 0; i < 6; i++) {
            float4 r; r.x = accO[i][0]; r.y = accO[i][1]; r.z = accO[i][2]; r.w = accO[i][3];
            *reinterpret_cast<float4*>(ao + base + (size_t)(i0 + i) * DD + d0) = r;
        }
    }
}

// ---------------- LayerNorm over D=512, warp per row ----------------
__global__ void __launch_bounds__(256) ln_kernel(
    const float* __restrict__ x, const float* __restrict__ gw, const float* __restrict__ bw,
    float* __restrict__ out)
{
    const int row  = blockIdx.x * 8 + (threadIdx.x >> 5);
    const int lane = threadIdx.x & 31;
    const float* xr = x + (size_t)row * DD;
    float4 v[4];
    float s = 0.f, s2 = 0.f;
    #pragma unroll
    for (int t = 0; t < 4; t++) {
        v[t] = *reinterpret_cast<const float4*>(xr + (size_t)(t * 32 + lane) * 4);
        s  += v[t].x + v[t].y + v[t].z + v[t].w;
        s2 += v[t].x * v[t].x + v[t].y * v[t].y + v[t].z * v[t].z + v[t].w * v[t].w;
    }
    #pragma unroll
    for (int o = 16; o > 0; o >>= 1) {
        s  += __shfl_xor_sync(0xffffffffu, s,  o);
        s2 += __shfl_xor_sync(0xffffffffu, s2, o);
    }
    const float mean = s * (1.f / DD);
    const float var  = s2 * (1.f / DD) - mean * mean;
    const float rstd = rsqrtf(var + EPS_LN);
    float* orow = out + (size_t)row * DD;
    #pragma unroll
    for (int t = 0; t < 4; t++) {
        int c = (t * 32 + lane) * 4;
        float4 gv = *reinterpret_cast<const float4*>(gw + c);
        float4 bv = *reinterpret_cast<const float4*>(bw + c);
        float4 r;
        r.x = (v[t].x - mean) * rstd * gv.x + bv.x;
        r.y = (v[t].y - mean) * rstd * gv.y + bv.y;
        r.z = (v[t].z - mean) * rstd * gv.z + bv.z;
        r.w = (v[t].w - mean) * rstd * gv.w + bv.w;
        *reinterpret_cast<float4*>(orow + c) = r;
    }
}

// ---------------- launch ----------------
extern "C" void kernel_launch(void* const* d_in, const int* in_sizes, int n_in,
                              void* d_out, int out_size)
{
    const float* src  = (const float*)d_in[0];
    const float* Wq   = (const float*)d_in[1];  const float* bq  = (const float*)d_in[2];
    const float* Wk   = (const float*)d_in[3];  const float* bk  = (const float*)d_in[4];
    const float* Wv   = (const float*)d_in[5];  const float* bv  = (const float*)d_in[6];
    const float* mat  = (const float*)d_in[7];
    const float* Wo   = (const float*)d_in[8];  const float* bo  = (const float*)d_in[9];
    const float* ln1g = (const float*)d_in[10]; const float* ln1b = (const float*)d_in[11];
    const float* W1   = (const float*)d_in[12]; const float* b1  = (const float*)d_in[13];
    const float* W2   = (const float*)d_in[14]; const float* b2  = (const float*)d_in[15];
    const float* ln2g = (const float*)d_in[16]; const float* ln2b = (const float*)d_in[17];

    float* y_out = (float*)d_out;
    float* scores_out = y_out + (size_t)NT * DD;

    float *q, *k, *v, *ao, *t, *x, *ff;
    cudaGetSymbolAddress((void**)&q,  g_q);
    cudaGetSymbolAddress((void**)&k,  g_k);
    cudaGetSymbolAddress((void**)&v,  g_v);
    cudaGetSymbolAddress((void**)&ao, g_ao);
    cudaGetSymbolAddress((void**)&t,  g_t);
    cudaGetSymbolAddress((void**)&x,  g_x);
    cudaGetSymbolAddress((void**)&ff, g_ff);

    cudaFuncSetAttribute(attn_kernel, cudaFuncAttributeMaxDynamicSharedMemorySize, SMEM_ATTN);

    dim3 g512(DD / 128, NT / 128);    // (4, 192)
    dim3 gff (DFF / 128, NT / 128);   // (16, 192)

    // QKV
    sgemm_kernel<0><<<g512, 256>>>(src, Wq, bq, nullptr, q, NT, DD, DD);
    sgemm_kernel<0><<<g512, 256>>>(src, Wk, bk, nullptr, k, NT, DD, DD);
    sgemm_kernel<0><<<g512, 256>>>(src, Wv, bv, nullptr, v, NT, DD, DD);
    // attention (writes scores + attn output)
    attn_kernel<<<BB * HH, 256, SMEM_ATTN>>>(q, k, v, mat, scores_out, ao);
    // output proj + residual, then LN1
    sgemm_kernel<2><<<g512, 256>>>(ao, Wo, bo, src, t, NT, DD, DD);
    ln_kernel<<<NT / 8, 256>>>(t, ln1g, ln1b, x);
    // FFN
    sgemm_kernel<1><<<gff, 256>>>(x, W1, b1, nullptr, ff, NT, DFF, DD);
    sgemm_kernel<2><<<g512, 256>>>(ff, W2, b2, x, t, NT, DD, DFF);
    ln_kernel<<<NT / 8, 256>>>(t, ln2g, ln2b, y_out);
}

// round 2
// speedup vs baseline: 1.6103x; 1.6103x over previous
#include <cuda_runtime.h>
#include <cuda_bf16.h>
#include <math.h>
#include <stdint.h>

// ---------------- problem dims ----------------
#define BB 256
#define LL 96
#define DD 512
#define HH 8
#define HDIM 64
#define DFF 2048
#define NT (BB*LL)          // 24576 tokens
#define SCALE 0.125f
#define EPS_LN 1e-5f

// ---------------- scratch (no allocs allowed) ----------------
__device__ float g_q [NT*DD];
__device__ float g_k [NT*DD];
__device__ float g_v [NT*DD];
__device__ float g_ao[NT*DD];
__device__ float g_t [NT*DD];
__device__ float g_x [NT*DD];
__device__ float g_ff[NT*DFF];

// ---------------- tf32 MMA GEMM: C = A[M,K] @ W[K,N] + bias (+epi) ----------------
// CTA tile 256x128, BK=16, 512 threads, 16 warps in 4x4 grid, warp tile 64x32.
#define BM 256
#define BN 128
#define BK 16
#define PADM 257
#define PADN 132

__device__ __forceinline__ uint32_t f2tf(float x) {
    uint32_t r;
    asm("cvt.rna.tf32.f32 %0, %1;" : "=r"(r) : "f"(x));
    return r;
}

__device__ __forceinline__ void mma_tf32(float* c, const uint32_t* a, const uint32_t* b) {
    asm volatile(
        "mma.sync.aligned.m16n8k8.row.col.f32.tf32.tf32.f32 "
        "{%0,%1,%2,%3}, {%4,%5,%6,%7}, {%8,%9}, {%0,%1,%2,%3};\n"
        : "+f"(c[0]), "+f"(c[1]), "+f"(c[2]), "+f"(c[3])
        : "r"(a[0]), "r"(a[1]), "r"(a[2]), "r"(a[3]), "r"(b[0]), "r"(b[1]));
}

__device__ __forceinline__ float gelu_exact(float x) {
    return 0.5f * x * (1.f + erff(x * 0.70710678118654752f));
}

// EPI: 0 = bias, 1 = bias + gelu, 2 = bias + residual
template<int EPI>
__device__ __forceinline__ void gemm_body(
    const float* __restrict__ A, const float* __restrict__ W,
    const float* __restrict__ bias, const float* __restrict__ resid,
    float* __restrict__ C, int N, int K)
{
    __shared__ uint32_t As[BK * PADM];   // [k][m], tf32 bits
    __shared__ uint32_t Bs[BK * PADN];   // [k][n], tf32 bits

    const int tid  = threadIdx.x;
    const int lane = tid & 31;
    const int wid  = tid >> 5;           // 0..15
    const int wm   = wid >> 2;           // 0..3  (M)
    const int wn   = wid & 3;            // 0..3  (N)
    const int lq   = lane & 3;           // k-sub
    const int lg   = lane >> 2;          // group 0..7

    const float* Ablk = A + (size_t)blockIdx.y * BM * K;
    const float* Wblk = W + (size_t)blockIdx.x * BN;

    float acc[4][4][4];
    #pragma unroll
    for (int mt = 0; mt < 4; mt++)
        #pragma unroll
        for (int nt = 0; nt < 4; nt++)
            #pragma unroll
            for (int r = 0; r < 4; r++) acc[mt][nt][r] = 0.f;

    // A-tile addressing: two float4 slots per thread
    const int fa0 = tid,        ra0 = fa0 >> 2, ca0 = (fa0 & 3) * 4;
    const int fa1 = tid + 512,  ra1 = fa1 >> 2, ca1 = (fa1 & 3) * 4;
    // B-tile: one float4 per thread
    const int rb = tid >> 5, cb = (tid & 31) * 4;

    float4 ga0, ga1, gb;
    // prologue load (k0 = 0)
    ga0 = *reinterpret_cast<const float4*>(Ablk + (size_t)ra0 * K + ca0);
    ga1 = *reinterpret_cast<const float4*>(Ablk + (size_t)ra1 * K + ca1);
    gb  = *reinterpret_cast<const float4*>(Wblk + (size_t)rb * N + cb);

    for (int k0 = 0; k0 < K; k0 += BK) {
        // store (with tf32 convert)
        As[(ca0 + 0) * PADM + ra0] = f2tf(ga0.x);
        As[(ca0 + 1) * PADM + ra0] = f2tf(ga0.y);
        As[(ca0 + 2) * PADM + ra0] = f2tf(ga0.z);
        As[(ca0 + 3) * PADM + ra0] = f2tf(ga0.w);
        As[(ca1 + 0) * PADM + ra1] = f2tf(ga1.x);
        As[(ca1 + 1) * PADM + ra1] = f2tf(ga1.y);
        As[(ca1 + 2) * PADM + ra1] = f2tf(ga1.z);
        As[(ca1 + 3) * PADM + ra1] = f2tf(ga1.w);
        {
            uint4 u;
            u.x = f2tf(gb.x); u.y = f2tf(gb.y); u.z = f2tf(gb.z); u.w = f2tf(gb.w);
            *reinterpret_cast<uint4*>(Bs + rb * PADN + cb) = u;
        }
        __syncthreads();

        // prefetch next tile while computing this one
        if (k0 + BK < K) {
            int kn = k0 + BK;
            ga0 = *reinterpret_cast<const float4*>(Ablk + (size_t)ra0 * K + kn + ca0);
            ga1 = *reinterpret_cast<const float4*>(Ablk + (size_t)ra1 * K + kn + ca1);
            gb  = *reinterpret_cast<const float4*>(Wblk + (size_t)(kn + rb) * N + cb);
        }

        #pragma unroll
        for (int q0 = 0; q0 < BK; q0 += 8) {
            uint32_t af[4][4], bf[4][2];
            const int kq = q0 + lq;
            #pragma unroll
            for (int mt = 0; mt < 4; mt++) {
                int m = wm * 64 + mt * 16 + lg;
                af[mt][0] = As[kq * PADM + m];
                af[mt][1] = As[kq * PADM + m + 8];
                af[mt][2] = As[(kq + 4) * PADM + m];
                af[mt][3] = As[(kq + 4) * PADM + m + 8];
            }
            #pragma unroll
            for (int nt = 0; nt < 4; nt++) {
                int n = wn * 32 + nt * 8 + lg;
                bf[nt][0] = Bs[kq * PADN + n];
                bf[nt][1] = Bs[(kq + 4) * PADN + n];
            }
            #pragma unroll
            for (int mt = 0; mt < 4; mt++)
                #pragma unroll
                for (int nt = 0; nt < 4; nt++)
                    mma_tf32(acc[mt][nt], af[mt], bf[nt]);
        }
        __syncthreads();
    }

    // epilogue: c0,c1 -> (row, col..col+1); c2,c3 -> (row+8, ...)
    #pragma unroll
    for (int mt = 0; mt < 4; mt++) {
        #pragma unroll
        for (int nt = 0; nt < 4; nt++) {
            int row = blockIdx.y * BM + wm * 64 + mt * 16 + lg;
            int col = blockIdx.x * BN + wn * 32 + nt * 8 + 2 * lq;
            float2 bv = *reinterpret_cast<const float2*>(bias + col);
            #pragma unroll
            for (int half = 0; half < 2; half++) {
                int r = row + half * 8;
                float2 o;
                o.x = acc[mt][nt][half * 2 + 0] + bv.x;
                o.y = acc[mt][nt][half * 2 + 1] + bv.y;
                if (EPI == 1) { o.x = gelu_exact(o.x); o.y = gelu_exact(o.y); }
                if (EPI == 2) {
                    float2 rv = *reinterpret_cast<const float2*>(resid + (size_t)r * N + col);
                    o.x += rv.x; o.y += rv.y;
                }
                *reinterpret_cast<float2*>(C + (size_t)r * N + col) = o;
            }
        }
    }
}

// Fused Q/K/V: blockIdx.z selects weight/bias/output
__global__ void __launch_bounds__(512, 1) qkv_kernel(
    const float* __restrict__ src,
    const float* __restrict__ Wq, const float* __restrict__ bq,
    const float* __restrict__ Wk, const float* __restrict__ bk,
    const float* __restrict__ Wv, const float* __restrict__ bv,
    float* __restrict__ q, float* __restrict__ k, float* __restrict__ v)
{
    const float* W; const float* b; float* out;
    if (blockIdx.z == 0)      { W = Wq; b = bq; out = q; }
    else if (blockIdx.z == 1) { W = Wk; b = bk; out = k; }
    else                      { W = Wv; b = bv; out = v; }
    gemm_body<0>(src, W, b, nullptr, out, DD, DD);
}

template<int EPI>
__global__ void __launch_bounds__(512, 1) gemm_kernel(
    const float* __restrict__ A, const float* __restrict__ W,
    const float* __restrict__ bias, const float* __restrict__ resid,
    float* __restrict__ C, int N, int K)
{
    gemm_body<EPI>(A, W, bias, resid, C, N, K);
}

// ---------------- fused attention per (b,h) (unchanged from R1) ----------------
#define SQ_LD 65
#define SS_LD 97
#define SMEM_ATTN ((2*LL*SQ_LD + LL*SS_LD + LL*HDIM) * (int)sizeof(float))

__global__ void __launch_bounds__(256) attn_kernel(
    const float* __restrict__ q, const float* __restrict__ k, const float* __restrict__ v,
    const float* __restrict__ matrix, float* __restrict__ scores_out, float* __restrict__ ao)
{
    extern __shared__ float sm[];
    float* qs = sm;
    float* ks = qs + LL * SQ_LD;
    float* ss = ks + LL * SQ_LD;
    float* vs = ss + LL * SS_LD;

    const int bh = blockIdx.x;
    const int b = bh / HH, h = bh % HH;
    const int tid = threadIdx.x;
    const size_t base = ((size_t)b * LL) * DD + h * HDIM;

    for (int idx = tid; idx < LL * HDIM; idx += 256) {
        int l = idx >> 6, d = idx & 63;
        size_t g = base + (size_t)l * DD + d;
        qs[l * SQ_LD + d] = q[g];
        ks[l * SQ_LD + d] = k[g];
        vs[l * HDIM  + d] = v[g];
    }
    __syncthreads();

    const float* mb  = matrix     + (size_t)bh * LL * LL;
    float*       sob = scores_out + (size_t)bh * LL * LL;

    {
        const int ti = tid >> 4, tj = tid & 15;
        const int i0 = ti * 6, j0 = tj * 6;
        float accS[6][6];
        #pragma unroll
        for (int i = 0; i < 6; i++)
            #pragma unroll
            for (int j = 0; j < 6; j++) accS[i][j] = 0.f;
        #pragma unroll 8
        for (int kk = 0; kk < HDIM; kk++) {
            float ar[6], br[6];
            #pragma unroll
            for (int i = 0; i < 6; i++) ar[i] = qs[(i0 + i) * SQ_LD + kk];
            #pragma unroll
            for (int j = 0; j < 6; j++) br[j] = ks[(j0 + j) * SQ_LD + kk];
            #pragma unroll
            for (int i = 0; i < 6; i++)
                #pragma unroll
                for (int j = 0; j < 6; j++)
                    accS[i][j] = fmaf(ar[i], br[j], accS[i][j]);
        }
        #pragma unroll
        for (int i = 0; i < 6; i++)
            #pragma unroll
            for (int j = 0; j < 6; j++) {
                int idx = (i0 + i) * LL + (j0 + j);
                float s = accS[i][j] * mb[idx] * SCALE;
                sob[idx] = s;
                ss[(i0 + i) * SS_LD + (j0 + j)] = s;
            }
    }
    __syncthreads();

    {
        const int w = tid >> 5, lane = tid & 31;
        for (int r = w; r < LL; r += 8) {
            float vals[3];
            float m = -1e30f;
            #pragma unroll
            for (int t = 0; t < 3; t++) {
                vals[t] = ss[r * SS_LD + lane + t * 32];
                m = fmaxf(m, vals[t]);
            }
            #pragma unroll
            for (int o = 16; o > 0; o >>= 1) m = fmaxf(m, __shfl_xor_sync(0xffffffffu, m, o));
            float sum = 0.f;
            #pragma unroll
            for (int t = 0; t < 3; t++) { vals[t] = __expf(vals[t] - m); sum += vals[t]; }
            #pragma unroll
            for (int o = 16; o > 0; o >>= 1) sum += __shfl_xor_sync(0xffffffffu, sum, o);
            float inv = 1.f / sum;
            #pragma unroll
            for (int t = 0; t < 3; t++) ss[r * SS_LD + lane + t * 32] = vals[t] * inv;
        }
    }
    __syncthreads();

    {
        const int ti = tid >> 4, tj = tid & 15;
        const int i0 = ti * 6, d0 = tj * 4;
        float accO[6][4];
        #pragma unroll
        for (int i = 0; i < 6; i++)
            #pragma unroll
            for (int d = 0; d < 4; d++) accO[i][d] = 0.f;
        #pragma unroll 4
        for (int kk = 0; kk < LL; kk++) {
            float4 bv = *reinterpret_cast<const float4*>(vs + kk * HDIM + d0);
            float ar[6];
            #pragma unroll
            for (int i = 0; i < 6; i++) ar[i] = ss[(i0 + i) * SS_LD + kk];
            #pragma unroll
            for (int i = 0; i < 6; i++) {
                accO[i][0] = fmaf(ar[i], bv.x, accO[i][0]);
                accO[i][1] = fmaf(ar[i], bv.y, accO[i][1]);
                accO[i][2] = fmaf(ar[i], bv.z, accO[i][2]);
                accO[i][3] = fmaf(ar[i], bv.w, accO[i][3]);
            }
        }
        #pragma unroll
        for (int i = 0; i < 6; i++) {
            float4 r; r.x = accO[i][0]; r.y = accO[i][1]; r.z = accO[i][2]; r.w = accO[i][3];
            *reinterpret_cast<float4*>(ao + base + (size_t)(i0 + i) * DD + d0) = r;
        }
    }
}

// ---------------- LayerNorm over D=512, warp per row ----------------
__global__ void __launch_bounds__(256) ln_kernel(
    const float* __restrict__ x, const float* __restrict__ gw, const float* __restrict__ bw,
    float* __restrict__ out)
{
    const int row  = blockIdx.x * 8 + (threadIdx.x >> 5);
    const int lane = threadIdx.x & 31;
    const float* xr = x + (size_t)row * DD;
    float4 v[4];
    float s = 0.f, s2 = 0.f;
    #pragma unroll
    for (int t = 0; t < 4; t++) {
        v[t] = *reinterpret_cast<const float4*>(xr + (size_t)(t * 32 + lane) * 4);
        s  += v[t].x + v[t].y + v[t].z + v[t].w;
        s2 += v[t].x * v[t].x + v[t].y * v[t].y + v[t].z * v[t].z + v[t].w * v[t].w;
    }
    #pragma unroll
    for (int o = 16; o > 0; o >>= 1) {
        s  += __shfl_xor_sync(0xffffffffu, s,  o);
        s2 += __shfl_xor_sync(0xffffffffu, s2, o);
    }
    const float mean = s * (1.f / DD);
    const float var  = s2 * (1.f / DD) - mean * mean;
    const float rstd = rsqrtf(var + EPS_LN);
    float* orow = out + (size_t)row * DD;
    #pragma unroll
    for (int t = 0; t < 4; t++) {
        int c = (t * 32 + lane) * 4;
        float4 gv = *reinterpret_cast<const float4*>(gw + c);
        float4 bv = *reinterpret_cast<const float4*>(bw + c);
        float4 r;
        r.x = (v[t].x - mean) * rstd * gv.x + bv.x;
        r.y = (v[t].y - mean) * rstd * gv.y + bv.y;
        r.z = (v[t].z - mean) * rstd * gv.z + bv.z;
        r.w = (v[t].w - mean) * rstd * gv.w + bv.w;
        *reinterpret_cast<float4*>(orow + c) = r;
    }
}

// ---------------- launch ----------------
extern "C" void kernel_launch(void* const* d_in, const int* in_sizes, int n_in,
                              void* d_out, int out_size)
{
    const float* src  = (const float*)d_in[0];
    const float* Wq   = (const float*)d_in[1];  const float* bq  = (const float*)d_in[2];
    const float* Wk   = (const float*)d_in[3];  const float* bk  = (const float*)d_in[4];
    const float* Wv   = (const float*)d_in[5];  const float* bv  = (const float*)d_in[6];
    const float* mat  = (const float*)d_in[7];
    const float* Wo   = (const float*)d_in[8];  const float* bo  = (const float*)d_in[9];
    const float* ln1g = (const float*)d_in[10]; const float* ln1b = (const float*)d_in[11];
    const float* W1   = (const float*)d_in[12]; const float* b1  = (const float*)d_in[13];
    const float* W2   = (const float*)d_in[14]; const float* b2  = (const float*)d_in[15];
    const float* ln2g = (const float*)d_in[16]; const float* ln2b = (const float*)d_in[17];

    float* y_out = (float*)d_out;
    float* scores_out = y_out + (size_t)NT * DD;

    float *q, *k, *v, *ao, *t, *x, *ff;
    cudaGetSymbolAddress((void**)&q,  g_q);
    cudaGetSymbolAddress((void**)&k,  g_k);
    cudaGetSymbolAddress((void**)&v,  g_v);
    cudaGetSymbolAddress((void**)&ao, g_ao);
    cudaGetSymbolAddress((void**)&t,  g_t);
    cudaGetSymbolAddress((void**)&x,  g_x);
    cudaGetSymbolAddress((void**)&ff, g_ff);

    cudaFuncSetAttribute(attn_kernel, cudaFuncAttributeMaxDynamicSharedMemorySize, SMEM_ATTN);

    dim3 gqkv(DD / BN, NT / BM, 3);     // (4, 96, 3)
    dim3 g512(DD / BN, NT / BM);        // (4, 96)
    dim3 gff (DFF / BN, NT / BM);       // (16, 96)

    qkv_kernel<<<gqkv, 512>>>(src, Wq, bq, Wk, bk, Wv, bv, q, k, v);
    attn_kernel<<<BB * HH, 256, SMEM_ATTN>>>(q, k, v, mat, scores_out, ao);
    gemm_kernel<2><<<g512, 512>>>(ao, Wo, bo, src, t, DD, DD);
    ln_kernel<<<NT / 8, 256>>>(t, ln1g, ln1b, x);
    gemm_kernel<1><<<gff, 512>>>(x, W1, b1, nullptr, ff, DFF, DD);
    gemm_kernel<2><<<g512, 512>>>(ff, W2, b2, x, t, DD, DFF);
    ln_kernel<<<NT / 8, 256>>>(t, ln2g, ln2b, y_out);
}

// round 4
// speedup vs baseline: 2.6868x; 1.6685x over previous
#include <cuda_runtime.h>
#include <cuda_bf16.h>
#include <math.h>
#include <stdint.h>

// ---------------- problem dims ----------------
#define BB 256
#define LL 96
#define DD 512
#define HH 8
#define HDIM 64
#define DFF 2048
#define NT (BB*LL)          // 24576 tokens
#define SCALE 0.125f
#define EPS_LN 1e-5f

// ---------------- scratch (no allocs allowed) ----------------
__device__ float g_q [NT*DD];
__device__ float g_k [NT*DD];
__device__ float g_v [NT*DD];
__device__ float g_ao[NT*DD];
__device__ float g_t [NT*DD];
__device__ float g_x [NT*DD];
__device__ float g_ff[NT*DFF];

// ---------------- tf32 MMA GEMM, cp.async 4-stage ----------------
// CTA tile 128x128, BK=16, 256 threads, 8 warps (2x4), warp tile 64x32.
#define BM 128
#define BN 128
#define BK 16
#define STAGES 4
#define PADA 20     // floats per A row   (conflict-free: lg*20+lq distinct mod 32)
#define PADB 136    // floats per B row   (conflict-free: lq*8+lg distinct mod 32)
#define A_STAGE (BM*PADA)
#define B_STAGE (BK*PADB)
#define SMEM_GEMM ((STAGES*(A_STAGE+B_STAGE))*(int)sizeof(float))  // 75776 B

__device__ __forceinline__ uint32_t f2tf(float x) {
    uint32_t r;
    asm("cvt.rna.tf32.f32 %0, %1;" : "=r"(r) : "f"(x));
    return r;
}

__device__ __forceinline__ void mma_tf32(float* c, const uint32_t* a, const uint32_t* b) {
    asm volatile(
        "mma.sync.aligned.m16n8k8.row.col.f32.tf32.tf32.f32 "
        "{%0,%1,%2,%3}, {%4,%5,%6,%7}, {%8,%9}, {%0,%1,%2,%3};\n"
        : "+f"(c[0]), "+f"(c[1]), "+f"(c[2]), "+f"(c[3])
        : "r"(a[0]), "r"(a[1]), "r"(a[2]), "r"(a[3]), "r"(b[0]), "r"(b[1]));
}

__device__ __forceinline__ void cp_async16(uint32_t dst, const void* src) {
    asm volatile("cp.async.cg.shared.global [%0], [%1], 16;" :: "r"(dst), "l"(src));
}
__device__ __forceinline__ void cp_commit() { asm volatile("cp.async.commit_group;"); }
__device__ __forceinline__ void cp_wait2()  { asm volatile("cp.async.wait_group 2;"); }

__device__ __forceinline__ float gelu_exact(float x) {
    return 0.5f * x * (1.f + erff(x * 0.70710678118654752f));
}

// EPI: 0 = bias, 1 = bias + gelu, 2 = bias + residual
template<int EPI>
__device__ __forceinline__ void gemm_body(
    const float* __restrict__ A, const float* __restrict__ W,
    const float* __restrict__ bias, const float* __restrict__ resid,
    float* __restrict__ C, int N, int K)
{
    extern __shared__ float smem[];
    float* As = smem;                          // STAGES x [128][PADA]
    float* Bs = smem + STAGES * A_STAGE;       // STAGES x [16][PADB]
    const uint32_t smemA = (uint32_t)__cvta_generic_to_shared(As);
    const uint32_t smemB = (uint32_t)__cvta_generic_to_shared(Bs);

    const int tid  = threadIdx.x;
    const int lane = tid & 31;
    const int wid  = tid >> 5;          // 0..7
    const int wm   = wid >> 2;          // 0..1
    const int wn   = wid & 3;           // 0..3
    const int lq   = lane & 3;
    const int lg   = lane >> 2;

    const float* Ablk = A + (size_t)blockIdx.y * BM * K;
    const float* Wblk = W + (size_t)blockIdx.x * BN;

    // loader addressing
    const int ra0 = tid >> 2,          ca0 = (tid & 3) * 4;           // A slot 0 (rows 0..63)
    const int ra1 = (tid + 256) >> 2,  ca1 = ca0;                     // A slot 1 (rows 64..127)
    const int rb0 = tid >> 5,          cb0 = (tid & 31) * 4;          // B slot 0 (rows 0..7)
    const int rb1 = (tid + 256) >> 5,  cb1 = cb0;                     // B slot 1 (rows 8..15)

    float acc[4][4][4];
    #pragma unroll
    for (int mt = 0; mt < 4; mt++)
        #pragma unroll
        for (int nt = 0; nt < 4; nt++)
            #pragma unroll
            for (int r = 0; r < 4; r++) acc[mt][nt][r] = 0.f;

    const int KT = K / BK;

    // prologue: fill stages 0..STAGES-2
    #pragma unroll
    for (int s = 0; s < STAGES - 1; s++) {
        int k0 = s * BK;
        cp_async16(smemA + (((s*BM + ra0)*PADA + ca0) << 2), Ablk + (size_t)ra0 * K + k0 + ca0);
        cp_async16(smemA + (((s*BM + ra1)*PADA + ca1) << 2), Ablk + (size_t)ra1 * K + k0 + ca1);
        cp_async16(smemB + (((s*BK + rb0)*PADB + cb0) << 2), Wblk + (size_t)(k0 + rb0) * N + cb0);
        cp_async16(smemB + (((s*BK + rb1)*PADB + cb1) << 2), Wblk + (size_t)(k0 + rb1) * N + cb1);
        cp_commit();
    }

    for (int kt = 0; kt < KT; kt++) {
        cp_wait2();
        __syncthreads();

        // issue loads for stage kt+STAGES-1 (overwrites the stage consumed at kt-1)
        int nk = kt + STAGES - 1;
        if (nk < KT) {
            int s = nk & (STAGES - 1);
            int k0 = nk * BK;
            cp_async16(smemA + (((s*BM + ra0)*PADA + ca0) << 2), Ablk + (size_t)ra0 * K + k0 + ca0);
            cp_async16(smemA + (((s*BM + ra1)*PADA + ca1) << 2), Ablk + (size_t)ra1 * K + k0 + ca1);
            cp_async16(smemB + (((s*BK + rb0)*PADB + cb0) << 2), Wblk + (size_t)(k0 + rb0) * N + cb0);
            cp_async16(smemB + (((s*BK + rb1)*PADB + cb1) << 2), Wblk + (size_t)(k0 + rb1) * N + cb1);
        }
        cp_commit();

        const float* as = As + (kt & (STAGES - 1)) * A_STAGE;
        const float* bs = Bs + (kt & (STAGES - 1)) * B_STAGE;

        #pragma unroll
        for (int q0 = 0; q0 < BK; q0 += 8) {
            const int kq = q0 + lq;
            uint32_t af[4][4], bf[4][2];
            #pragma unroll
            for (int mt = 0; mt < 4; mt++) {
                int m = wm * 64 + mt * 16 + lg;
                af[mt][0] = f2tf(as[m * PADA + kq]);
                af[mt][1] = f2tf(as[(m + 8) * PADA + kq]);
                af[mt][2] = f2tf(as[m * PADA + kq + 4]);
                af[mt][3] = f2tf(as[(m + 8) * PADA + kq + 4]);
            }
            #pragma unroll
            for (int nt = 0; nt < 4; nt++) {
                int n = wn * 32 + nt * 8 + lg;
                bf[nt][0] = f2tf(bs[kq * PADB + n]);
                bf[nt][1] = f2tf(bs[(kq + 4) * PADB + n]);
            }
            #pragma unroll
            for (int mt = 0; mt < 4; mt++)
                #pragma unroll
                for (int nt = 0; nt < 4; nt++)
                    mma_tf32(acc[mt][nt], af[mt], bf[nt]);
        }
    }

    // epilogue
    #pragma unroll
    for (int mt = 0; mt < 4; mt++) {
        #pragma unroll
        for (int nt = 0; nt < 4; nt++) {
            int row = blockIdx.y * BM + wm * 64 + mt * 16 + lg;
            int col = blockIdx.x * BN + wn * 32 + nt * 8 + 2 * lq;
            float2 bv = *reinterpret_cast<const float2*>(bias + col);
            #pragma unroll
            for (int half = 0; half < 2; half++) {
                int r = row + half * 8;
                float2 o;
                o.x = acc[mt][nt][half * 2 + 0] + bv.x;
                o.y = acc[mt][nt][half * 2 + 1] + bv.y;
                if (EPI == 1) { o.x = gelu_exact(o.x); o.y = gelu_exact(o.y); }
                if (EPI == 2) {
                    float2 rv = *reinterpret_cast<const float2*>(resid + (size_t)r * N + col);
                    o.x += rv.x; o.y += rv.y;
                }
                *reinterpret_cast<float2*>(C + (size_t)r * N + col) = o;
            }
        }
    }
}

__global__ void __launch_bounds__(256, 2) qkv_kernel(
    const float* __restrict__ src,
    const float* __restrict__ Wq, const float* __restrict__ bq,
    const float* __restrict__ Wk, const float* __restrict__ bk,
    const float* __restrict__ Wv, const float* __restrict__ bv,
    float* __restrict__ q, float* __restrict__ k, float* __restrict__ v)
{
    const float* W; const float* b; float* out;
    if (blockIdx.z == 0)      { W = Wq; b = bq; out = q; }
    else if (blockIdx.z == 1) { W = Wk; b = bk; out = k; }
    else                      { W = Wv; b = bv; out = v; }
    gemm_body<0>(src, W, b, nullptr, out, DD, DD);
}

template<int EPI>
__global__ void __launch_bounds__(256, 2) gemm_kernel(
    const float* __restrict__ A, const float* __restrict__ W,
    const float* __restrict__ bias, const float* __restrict__ resid,
    float* __restrict__ C, int N, int K)
{
    gemm_body<EPI>(A, W, bias, resid, C, N, K);
}

// ---------------- fused attention per (b,h) ----------------
#define SQ_LD 65
#define SS_LD 97
#define SMEM_ATTN ((2*LL*SQ_LD + LL*SS_LD + LL*HDIM) * (int)sizeof(float))

__global__ void __launch_bounds__(256) attn_kernel(
    const float* __restrict__ q, const float* __restrict__ k, const float* __restrict__ v,
    const float* __restrict__ matrix, float* __restrict__ scores_out, float* __restrict__ ao)
{
    extern __shared__ float sm[];
    float* qs = sm;
    float* ks = qs + LL * SQ_LD;
    float* ss = ks + LL * SQ_LD;
    float* vs = ss + LL * SS_LD;

    const int bh = blockIdx.x;
    const int b = bh / HH, h = bh % HH;
    const int tid = threadIdx.x;
    const size_t base = ((size_t)b * LL) * DD + h * HDIM;

    for (int idx = tid; idx < LL * HDIM; idx += 256) {
        int l = idx >> 6, d = idx & 63;
        size_t g = base + (size_t)l * DD + d;
        qs[l * SQ_LD + d] = q[g];
        ks[l * SQ_LD + d] = k[g];
        vs[l * HDIM  + d] = v[g];
    }
    __syncthreads();

    const float* mb  = matrix     + (size_t)bh * LL * LL;
    float*       sob = scores_out + (size_t)bh * LL * LL;

    {
        const int ti = tid >> 4, tj = tid & 15;
        const int i0 = ti * 6, j0 = tj * 6;
        float accS[6][6];
        #pragma unroll
        for (int i = 0; i < 6; i++)
            #pragma unroll
            for (int j = 0; j < 6; j++) accS[i][j] = 0.f;
        #pragma unroll 8
        for (int kk = 0; kk < HDIM; kk++) {
            float ar[6], br[6];
            #pragma unroll
            for (int i = 0; i < 6; i++) ar[i] = qs[(i0 + i) * SQ_LD + kk];
            #pragma unroll
            for (int j = 0; j < 6; j++) br[j] = ks[(j0 + j) * SQ_LD + kk];
            #pragma unroll
            for (int i = 0; i < 6; i++)
                #pragma unroll
                for (int j = 0; j < 6; j++)
                    accS[i][j] = fmaf(ar[i], br[j], accS[i][j]);
        }
        #pragma unroll
        for (int i = 0; i < 6; i++)
            #pragma unroll
            for (int j = 0; j < 6; j++) {
                int idx = (i0 + i) * LL + (j0 + j);
                float s = accS[i][j] * mb[idx] * SCALE;
                sob[idx] = s;
                ss[(i0 + i) * SS_LD + (j0 + j)] = s;
            }
    }
    __syncthreads();

    {
        const int w = tid >> 5, lane = tid & 31;
        for (int r = w; r < LL; r += 8) {
            float vals[3];
            float m = -1e30f;
            #pragma unroll
            for (int t = 0; t < 3; t++) {
                vals[t] = ss[r * SS_LD + lane + t * 32];
                m = fmaxf(m, vals[t]);
            }
            #pragma unroll
            for (int o = 16; o > 0; o >>= 1) m = fmaxf(m, __shfl_xor_sync(0xffffffffu, m, o));
            float sum = 0.f;
            #pragma unroll
            for (int t = 0; t < 3; t++) { vals[t] = __expf(vals[t] - m); sum += vals[t]; }
            #pragma unroll
            for (int o = 16; o > 0; o >>= 1) sum += __shfl_xor_sync(0xffffffffu, sum, o);
            float inv = 1.f / sum;
            #pragma unroll
            for (int t = 0; t < 3; t++) ss[r * SS_LD + lane + t * 32] = vals[t] * inv;
        }
    }
    __syncthreads();

    {
        const int ti = tid >> 4, tj = tid & 15;
        const int i0 = ti * 6, d0 = tj * 4;
        float accO[6][4];
        #pragma unroll
        for (int i = 0; i < 6; i++)
            #pragma unroll
            for (int d = 0; d < 4; d++) accO[i][d] = 0.f;
        #pragma unroll 4
        for (int kk = 0; kk < LL; kk++) {
            float4 bv = *reinterpret_cast<const float4*>(vs + kk * HDIM + d0);
            float ar[6];
            #pragma unroll
            for (int i = 0; i < 6; i++) ar[i] = ss[(i0 + i) * SS_LD + kk];
            #pragma unroll
            for (int i = 0; i < 6; i++) {
                accO[i][0] = fmaf(ar[i], bv.x, accO[i][0]);
                accO[i][1] = fmaf(ar[i], bv.y, accO[i][1]);
                accO[i][2] = fmaf(ar[i], bv.z, accO[i][2]);
                accO[i][3] = fmaf(ar[i], bv.w, accO[i][3]);
            }
        }
        #pragma unroll
        for (int i = 0; i < 6; i++) {
            float4 r; r.x = accO[i][0]; r.y = accO[i][1]; r.z = accO[i][2]; r.w = accO[i][3];
            *reinterpret_cast<float4*>(ao + base + (size_t)(i0 + i) * DD + d0) = r;
        }
    }
}

// ---------------- LayerNorm over D=512, warp per row ----------------
__global__ void __launch_bounds__(256) ln_kernel(
    const float* __restrict__ x, const float* __restrict__ gw, const float* __restrict__ bw,
    float* __restrict__ out)
{
    const int row  = blockIdx.x * 8 + (threadIdx.x >> 5);
    const int lane = threadIdx.x & 31;
    const float* xr = x + (size_t)row * DD;
    float4 v[4];
    float s = 0.f, s2 = 0.f;
    #pragma unroll
    for (int t = 0; t < 4; t++) {
        v[t] = *reinterpret_cast<const float4*>(xr + (size_t)(t * 32 + lane) * 4);
        s  += v[t].x + v[t].y + v[t].z + v[t].w;
        s2 += v[t].x * v[t].x + v[t].y * v[t].y + v[t].z * v[t].z + v[t].w * v[t].w;
    }
    #pragma unroll
    for (int o = 16; o > 0; o >>= 1) {
        s  += __shfl_xor_sync(0xffffffffu, s,  o);
        s2 += __shfl_xor_sync(0xffffffffu, s2, o);
    }
    const float mean = s * (1.f / DD);
    const float var  = s2 * (1.f / DD) - mean * mean;
    const float rstd = rsqrtf(var + EPS_LN);
    float* orow = out + (size_t)row * DD;
    #pragma unroll
    for (int t = 0; t < 4; t++) {
        int c = (t * 32 + lane) * 4;
        float4 gv = *reinterpret_cast<const float4*>(gw + c);
        float4 bv = *reinterpret_cast<const float4*>(bw + c);
        float4 r;
        r.x = (v[t].x - mean) * rstd * gv.x + bv.x;
        r.y = (v[t].y - mean) * rstd * gv.y + bv.y;
        r.z = (v[t].z - mean) * rstd * gv.z + bv.z;
        r.w = (v[t].w - mean) * rstd * gv.w + bv.w;
        *reinterpret_cast<float4*>(orow + c) = r;
    }
}

// ---------------- launch ----------------
extern "C" void kernel_launch(void* const* d_in, const int* in_sizes, int n_in,
                              void* d_out, int out_size)
{
    const float* src  = (const float*)d_in[0];
    const float* Wq   = (const float*)d_in[1];  const float* bq  = (const float*)d_in[2];
    const float* Wk   = (const float*)d_in[3];  const float* bk  = (const float*)d_in[4];
    const float* Wv   = (const float*)d_in[5];  const float* bv  = (const float*)d_in[6];
    const float* mat  = (const float*)d_in[7];
    const float* Wo   = (const float*)d_in[8];  const float* bo  = (const float*)d_in[9];
    const float* ln1g = (const float*)d_in[10]; const float* ln1b = (const float*)d_in[11];
    const float* W1   = (const float*)d_in[12]; const float* b1  = (const float*)d_in[13];
    const float* W2   = (const float*)d_in[14]; const float* b2  = (const float*)d_in[15];
    const float* ln2g = (const float*)d_in[16]; const float* ln2b = (const float*)d_in[17];

    float* y_out = (float*)d_out;
    float* scores_out = y_out + (size_t)NT * DD;

    float *q, *k, *v, *ao, *t, *x, *ff;
    cudaGetSymbolAddress((void**)&q,  g_q);
    cudaGetSymbolAddress((void**)&k,  g_k);
    cudaGetSymbolAddress((void**)&v,  g_v);
    cudaGetSymbolAddress((void**)&ao, g_ao);
    cudaGetSymbolAddress((void**)&t,  g_t);
    cudaGetSymbolAddress((void**)&x,  g_x);
    cudaGetSymbolAddress((void**)&ff, g_ff);

    cudaFuncSetAttribute(qkv_kernel,     cudaFuncAttributeMaxDynamicSharedMemorySize, SMEM_GEMM);
    cudaFuncSetAttribute(gemm_kernel<1>, cudaFuncAttributeMaxDynamicSharedMemorySize, SMEM_GEMM);
    cudaFuncSetAttribute(gemm_kernel<2>, cudaFuncAttributeMaxDynamicSharedMemorySize, SMEM_GEMM);
    cudaFuncSetAttribute(attn_kernel,    cudaFuncAttributeMaxDynamicSharedMemorySize, SMEM_ATTN);

    dim3 gqkv(DD / BN, NT / BM, 3);     // (4, 192, 3)
    dim3 g512(DD / BN, NT / BM);        // (4, 192)
    dim3 gff (DFF / BN, NT / BM);       // (16, 192)

    qkv_kernel<<<gqkv, 256, SMEM_GEMM>>>(src, Wq, bq, Wk, bk, Wv, bv, q, k, v);
    attn_kernel<<<BB * HH, 256, SMEM_ATTN>>>(q, k, v, mat, scores_out, ao);
    gemm_kernel<2><<<g512, 256, SMEM_GEMM>>>(ao, Wo, bo, src, t, DD, DD);
    ln_kernel<<<NT / 8, 256>>>(t, ln1g, ln1b, x);
    gemm_kernel<1><<<gff, 256, SMEM_GEMM>>>(x, W1, b1, nullptr, ff, DFF, DD);
    gemm_kernel<2><<<g512, 256, SMEM_GEMM>>>(ff, W2, b2, x, t, DD, DFF);
    ln_kernel<<<NT / 8, 256>>>(t, ln2g, ln2b, y_out);
}

// round 6
// speedup vs baseline: 4.3538x; 1.6205x over previous
#include <cuda_runtime.h>
#include <cuda_fp16.h>
#include <math.h>
#include <stdint.h>

// ---------------- problem dims ----------------
#define BB 256
#define LL 96
#define DD 512
#define HH 8
#define HDIM 64
#define DFF 2048
#define NT (BB*LL)          // 24576 tokens
#define SCALE 0.125f
#define EPS_LN 1e-5f

// ---------------- scratch (no allocs allowed) ----------------
__device__ __align__(16) __half g_src16[NT*DD];
__device__ __align__(16) __half g_q16 [NT*DD];
__device__ __align__(16) __half g_k16 [NT*DD];
__device__ __align__(16) __half g_v16 [NT*DD];
__device__ __align__(16) __half g_ao16[NT*DD];
__device__ __align__(16) __half g_x16 [NT*DD];
__device__ __align__(16) __half g_ff16[NT*DFF];
__device__ float g_t [NT*DD];
__device__ float g_x [NT*DD];
__device__ __align__(16) __half g_wt16[4*DD*DD + 2*DD*DFF];   // transposed fp16 weights

// offsets into g_wt16 (halves)
#define WT_Q  0
#define WT_K  (DD*DD)
#define WT_V  (2*DD*DD)
#define WT_O  (3*DD*DD)
#define WT_1  (4*DD*DD)            // W1T [2048,512]
#define WT_2  (4*DD*DD + DD*DFF)   // W2T [512,2048]

struct h4 { __half2 a, b; };

// ---------------- helpers ----------------
__device__ __forceinline__ void cp_async16(uint32_t dst, const void* src) {
    asm volatile("cp.async.cg.shared.global [%0], [%1], 16;" :: "r"(dst), "l"(src));
}
__device__ __forceinline__ void cp_commit() { asm volatile("cp.async.commit_group;" ::: "memory"); }
__device__ __forceinline__ void cp_wait2()  { asm volatile("cp.async.wait_group 2;" ::: "memory"); }

__device__ __forceinline__ void mma_f16(float* c, const uint32_t* a, const uint32_t* b) {
    asm volatile(
        "mma.sync.aligned.m16n8k16.row.col.f32.f16.f16.f32 "
        "{%0,%1,%2,%3}, {%4,%5,%6,%7}, {%8,%9}, {%0,%1,%2,%3};\n"
        : "+f"(c[0]), "+f"(c[1]), "+f"(c[2]), "+f"(c[3])
        : "r"(a[0]), "r"(a[1]), "r"(a[2]), "r"(a[3]), "r"(b[0]), "r"(b[1]));
}

__device__ __forceinline__ float gelu_exact(float x) {
    return 0.5f * x * (1.f + erff(x * 0.70710678118654752f));
}

// ---------------- fp16 MMA GEMM, cp.async 4-stage ----------------
// CTA tile 128x128, BK=32 halves, 256 threads, 8 warps (2x4), warp tile 64x32.
// A [M,K] fp16 row-major; B = Wt [N,K] fp16 row-major (K contiguous -> mma "col" operand).
#define STAGES 4
#define ROWB 80                       // bytes per smem row (32 halves + 8 pad)
#define A_ST (128*ROWB)               // 10240 B
#define B_ST (128*ROWB)
#define SMEM_GEMM (STAGES*(A_ST+B_ST))  // 81920 B

// EPI: 0 = bias -> fp16 out; 1 = bias+gelu -> fp16 out; 2 = bias+residual -> fp32 out
template<int EPI>
__device__ __forceinline__ void gemm_body(
    const __half* __restrict__ A, const __half* __restrict__ Bt,
    const float* __restrict__ bias, const float* __restrict__ resid,
    void* __restrict__ Cout, int N, int K)
{
    extern __shared__ char smem[];
    const uint32_t smemA = (uint32_t)__cvta_generic_to_shared(smem);
    const uint32_t smemB = smemA + STAGES * A_ST;

    const int tid  = threadIdx.x;
    const int lane = tid & 31;
    const int wid  = tid >> 5;          // 0..7
    const int wm   = wid >> 2;          // 0..1
    const int wn   = wid & 3;           // 0..3
    const int lq   = lane & 3;          // k-pair (t)
    const int lg   = lane >> 2;         // group (g)

    const __half* Ablk = A  + (size_t)blockIdx.y * 128 * K;
    const __half* Bblk = Bt + (size_t)blockIdx.x * 128 * K;

    // loader: 512 16B-chunks per tile, 2 per thread per array
    const int r0 = tid >> 1,          c0 = (tid & 1) * 2;     // chunks 0,1 of row -> c16 in {0,1} or {2,3}
    // simpler: chunk index c in [0,512): r=c>>2, c16=c&3
    const int ca_r0 = tid >> 2,        ca_c0 = tid & 3;        // chunk tid
    const int ca_r1 = (tid + 256) >> 2, ca_c1 = (tid + 256) & 3;
    (void)r0; (void)c0;

    float acc[4][4][4];
    #pragma unroll
    for (int mt = 0; mt < 4; mt++)
        #pragma unroll
        for (int nt = 0; nt < 4; nt++)
            #pragma unroll
            for (int r = 0; r < 4; r++) acc[mt][nt][r] = 0.f;

    const int KT = K >> 5;   // K/32

    auto load_tile = [&](int kt) {
        const int s = kt & (STAGES - 1);
        const int kof = kt << 5;   // halves
        cp_async16(smemA + s*A_ST + ca_r0*ROWB + ca_c0*16, Ablk + (size_t)ca_r0 * K + kof + ca_c0*8);
        cp_async16(smemA + s*A_ST + ca_r1*ROWB + ca_c1*16, Ablk + (size_t)ca_r1 * K + kof + ca_c1*8);
        cp_async16(smemB + s*B_ST + ca_r0*ROWB + ca_c0*16, Bblk + (size_t)ca_r0 * K + kof + ca_c0*8);
        cp_async16(smemB + s*B_ST + ca_r1*ROWB + ca_c1*16, Bblk + (size_t)ca_r1 * K + kof + ca_c1*8);
    };

    // prologue: stages 0..STAGES-2
    #pragma unroll
    for (int s = 0; s < STAGES - 1; s++) { load_tile(s); cp_commit(); }

    for (int kt = 0; kt < KT; kt++) {
        cp_wait2();
        __syncthreads();

        int nk = kt + STAGES - 1;
        if (nk < KT) load_tile(nk);
        cp_commit();

        const char* as = smem + (kt & (STAGES - 1)) * A_ST;
        const char* bs = smem + STAGES * A_ST + (kt & (STAGES - 1)) * B_ST;

        #pragma unroll
        for (int q0 = 0; q0 < 32; q0 += 16) {
            const int kb = 2 * (q0 + 2 * lq);   // byte offset of k-pair in row
            uint32_t af[4][4], bf[4][2];
            #pragma unroll
            for (int mt = 0; mt < 4; mt++) {
                int m = wm * 64 + mt * 16 + lg;
                const char* p = as + m * ROWB + kb;
                af[mt][0] = *reinterpret_cast<const uint32_t*>(p);
                af[mt][1] = *reinterpret_cast<const uint32_t*>(p + 8 * ROWB);
                af[mt][2] = *reinterpret_cast<const uint32_t*>(p + 16);
                af[mt][3] = *reinterpret_cast<const uint32_t*>(p + 8 * ROWB + 16);
            }
            #pragma unroll
            for (int nt = 0; nt < 4; nt++) {
                int n = wn * 32 + nt * 8 + lg;
                const char* p = bs + n * ROWB + kb;
                bf[nt][0] = *reinterpret_cast<const uint32_t*>(p);
                bf[nt][1] = *reinterpret_cast<const uint32_t*>(p + 16);
            }
            #pragma unroll
            for (int mt = 0; mt < 4; mt++)
                #pragma unroll
                for (int nt = 0; nt < 4; nt++)
                    mma_f16(acc[mt][nt], af[mt], bf[nt]);
        }
    }

    // epilogue
    #pragma unroll
    for (int mt = 0; mt < 4; mt++) {
        #pragma unroll
        for (int nt = 0; nt < 4; nt++) {
            int row = blockIdx.y * 128 + wm * 64 + mt * 16 + lg;
            int col = blockIdx.x * 128 + wn * 32 + nt * 8 + 2 * lq;
            float2 bv = *reinterpret_cast<const float2*>(bias + col);
            #pragma unroll
            for (int half_i = 0; half_i < 2; half_i++) {
                int r = row + half_i * 8;
                float ox = acc[mt][nt][half_i * 2 + 0] + bv.x;
                float oy = acc[mt][nt][half_i * 2 + 1] + bv.y;
                if (EPI == 1) { ox = gelu_exact(ox); oy = gelu_exact(oy); }
                if (EPI == 2) {
                    float2 rv = *reinterpret_cast<const float2*>(resid + (size_t)r * N + col);
                    ox += rv.x; oy += rv.y;
                    *reinterpret_cast<float2*>((float*)Cout + (size_t)r * N + col) = make_float2(ox, oy);
                } else {
                    *reinterpret_cast<__half2*>((__half*)Cout + (size_t)r * N + col) =
                        __floats2half2_rn(ox, oy);
                }
            }
        }
    }
}

__global__ void __launch_bounds__(256, 2) qkv_kernel(
    const __half* __restrict__ src16, const __half* __restrict__ wt,
    const float* __restrict__ bq, const float* __restrict__ bk, const float* __restrict__ bv,
    __half* __restrict__ q, __half* __restrict__ k, __half* __restrict__ v)
{
    const __half* Bt; const float* b; __half* out;
    if (blockIdx.z == 0)      { Bt = wt + WT_Q; b = bq; out = q; }
    else if (blockIdx.z == 1) { Bt = wt + WT_K; b = bk; out = k; }
    else                      { Bt = wt + WT_V; b = bv; out = v; }
    gemm_body<0>(src16, Bt, b, nullptr, out, DD, DD);
}

template<int EPI>
__global__ void __launch_bounds__(256, 2) gemm_kernel(
    const __half* __restrict__ A, const __half* __restrict__ Bt,
    const float* __restrict__ bias, const float* __restrict__ resid,
    void* __restrict__ C, int N, int K)
{
    gemm_body<EPI>(A, Bt, bias, resid, C, N, K);
}

// ---------------- weight transpose fp32[K,N] -> fp16[N,K] ----------------
__global__ void __launch_bounds__(256) transpose16_kernel(
    const float* __restrict__ in, __half* __restrict__ out, int K, int N)
{
    __shared__ float t[32][33];
    const int tx = threadIdx.x, ty = threadIdx.y;   // 32x8
    const int x0 = blockIdx.x * 32, y0 = blockIdx.y * 32;
    #pragma unroll
    for (int j = 0; j < 4; j++)
        t[ty + 8 * j][tx] = in[(size_t)(y0 + ty + 8 * j) * N + x0 + tx];
    __syncthreads();
    #pragma unroll
    for (int j = 0; j < 4; j++)
        out[(size_t)(x0 + ty + 8 * j) * K + y0 + tx] = __float2half(t[tx][ty + 8 * j]);
}

// ---------------- fp32 -> fp16 convert ----------------
__global__ void __launch_bounds__(256) cvt16_kernel(
    const float* __restrict__ in, __half* __restrict__ out, int n4)
{
    int i = blockIdx.x * 256 + threadIdx.x;
    if (i < n4) {
        float4 v = reinterpret_cast<const float4*>(in)[i];
        h4 o;
        o.a = __floats2half2_rn(v.x, v.y);
        o.b = __floats2half2_rn(v.z, v.w);
        reinterpret_cast<h4*>(out)[i] = o;
    }
}

// ---------------- fused attention per (b,h) ----------------
#define SQ_LD 65
#define SS_LD 97
#define SMEM_ATTN ((2*LL*SQ_LD + LL*SS_LD + LL*HDIM) * (int)sizeof(float))

__global__ void __launch_bounds__(256) attn_kernel(
    const __half* __restrict__ q, const __half* __restrict__ k, const __half* __restrict__ v,
    const float* __restrict__ matrix, float* __restrict__ scores_out, __half* __restrict__ ao)
{
    extern __shared__ float sm[];
    float* qs = sm;
    float* ks = qs + LL * SQ_LD;
    float* ss = ks + LL * SQ_LD;
    float* vs = ss + LL * SS_LD;

    const int bh = blockIdx.x;
    const int b = bh / HH, h = bh % HH;
    const int tid = threadIdx.x;
    const size_t base = ((size_t)b * LL) * DD + h * HDIM;

    for (int idx = tid; idx < LL * HDIM; idx += 256) {
        int l = idx >> 6, d = idx & 63;
        size_t g = base + (size_t)l * DD + d;
        qs[l * SQ_LD + d] = __half2float(q[g]);
        ks[l * SQ_LD + d] = __half2float(k[g]);
        vs[l * HDIM  + d] = __half2float(v[g]);
    }
    __syncthreads();

    const float* mb  = matrix     + (size_t)bh * LL * LL;
    float*       sob = scores_out + (size_t)bh * LL * LL;

    {
        const int ti = tid >> 4, tj = tid & 15;
        const int i0 = ti * 6, j0 = tj * 6;
        float accS[6][6];
        #pragma unroll
        for (int i = 0; i < 6; i++)
            #pragma unroll
            for (int j = 0; j < 6; j++) accS[i][j] = 0.f;
        #pragma unroll 8
        for (int kk = 0; kk < HDIM; kk++) {
            float ar[6], br[6];
            #pragma unroll
            for (int i = 0; i < 6; i++) ar[i] = qs[(i0 + i) * SQ_LD + kk];
            #pragma unroll
            for (int j = 0; j < 6; j++) br[j] = ks[(j0 + j) * SQ_LD + kk];
            #pragma unroll
            for (int i = 0; i < 6; i++)
                #pragma unroll
                for (int j = 0; j < 6; j++)
                    accS[i][j] = fmaf(ar[i], br[j], accS[i][j]);
        }
        #pragma unroll
        for (int i = 0; i < 6; i++)
            #pragma unroll
            for (int j = 0; j < 6; j++) {
                int idx = (i0 + i) * LL + (j0 + j);
                float s = accS[i][j] * mb[idx] * SCALE;
                sob[idx] = s;
                ss[(i0 + i) * SS_LD + (j0 + j)] = s;
            }
    }
    __syncthreads();

    {
        const int w = tid >> 5, lane = tid & 31;
        for (int r = w; r < LL; r += 8) {
            float vals[3];
            float m = -1e30f;
            #pragma unroll
            for (int t = 0; t < 3; t++) {
                vals[t] = ss[r * SS_LD + lane + t * 32];
                m = fmaxf(m, vals[t]);
            }
            #pragma unroll
            for (int o = 16; o > 0; o >>= 1) m = fmaxf(m, __shfl_xor_sync(0xffffffffu, m, o));
            float sum = 0.f;
            #pragma unroll
            for (int t = 0; t < 3; t++) { vals[t] = __expf(vals[t] - m); sum += vals[t]; }
            #pragma unroll
            for (int o = 16; o > 0; o >>= 1) sum += __shfl_xor_sync(0xffffffffu, sum, o);
            float inv = 1.f / sum;
            #pragma unroll
            for (int t = 0; t < 3; t++) ss[r * SS_LD + lane + t * 32] = vals[t] * inv;
        }
    }
    __syncthreads();

    {
        const int ti = tid >> 4, tj = tid & 15;
        const int i0 = ti * 6, d0 = tj * 4;
        float accO[6][4];
        #pragma unroll
        for (int i = 0; i < 6; i++)
            #pragma unroll
            for (int d = 0; d < 4; d++) accO[i][d] = 0.f;
        #pragma unroll 4
        for (int kk = 0; kk < LL; kk++) {
            float4 bv = *reinterpret_cast<const float4*>(vs + kk * HDIM + d0);
            float ar[6];
            #pragma unroll
            for (int i = 0; i < 6; i++) ar[i] = ss[(i0 + i) * SS_LD + kk];
            #pragma unroll
            for (int i = 0; i < 6; i++) {
                accO[i][0] = fmaf(ar[i], bv.x, accO[i][0]);
                accO[i][1] = fmaf(ar[i], bv.y, accO[i][1]);
                accO[i][2] = fmaf(ar[i], bv.z, accO[i][2]);
                accO[i][3] = fmaf(ar[i], bv.w, accO[i][3]);
            }
        }
        #pragma unroll
        for (int i = 0; i < 6; i++) {
            h4 o;
            o.a = __floats2half2_rn(accO[i][0], accO[i][1]);
            o.b = __floats2half2_rn(accO[i][2], accO[i][3]);
            *reinterpret_cast<h4*>(ao + base + (size_t)(i0 + i) * DD + d0) = o;
        }
    }
}

// ---------------- LayerNorm over D=512, warp per row (optional fp16 dual-out) ----------------
__global__ void __launch_bounds__(256) ln_kernel(
    const float* __restrict__ x, const float* __restrict__ gw, const float* __restrict__ bw,
    float* __restrict__ out, __half* __restrict__ out16)
{
    const int row  = blockIdx.x * 8 + (threadIdx.x >> 5);
    const int lane = threadIdx.x & 31;
    const float* xr = x + (size_t)row * DD;
    float4 v[4];
    float s = 0.f, s2 = 0.f;
    #pragma unroll
    for (int t = 0; t < 4; t++) {
        v[t] = *reinterpret_cast<const float4*>(xr + (size_t)(t * 32 + lane) * 4);
        s  += v[t].x + v[t].y + v[t].z + v[t].w;
        s2 += v[t].x * v[t].x + v[t].y * v[t].y + v[t].z * v[t].z + v[t].w * v[t].w;
    }
    #pragma unroll
    for (int o = 16; o > 0; o >>= 1) {
        s  += __shfl_xor_sync(0xffffffffu, s,  o);
        s2 += __shfl_xor_sync(0xffffffffu, s2, o);
    }
    const float mean = s * (1.f / DD);
    const float var  = s2 * (1.f / DD) - mean * mean;
    const float rstd = rsqrtf(var + EPS_LN);
    float* orow = out + (size_t)row * DD;
    #pragma unroll
    for (int t = 0; t < 4; t++) {
        int c = (t * 32 + lane) * 4;
        float4 gv = *reinterpret_cast<const float4*>(gw + c);
        float4 bv = *reinterpret_cast<const float4*>(bw + c);
        float4 r;
        r.x = (v[t].x - mean) * rstd * gv.x + bv.x;
        r.y = (v[t].y - mean) * rstd * gv.y + bv.y;
        r.z = (v[t].z - mean) * rstd * gv.z + bv.z;
        r.w = (v[t].w - mean) * rstd * gv.w + bv.w;
        *reinterpret_cast<float4*>(orow + c) = r;
        if (out16) {
            h4 o;
            o.a = __floats2half2_rn(r.x, r.y);
            o.b = __floats2half2_rn(r.z, r.w);
            *reinterpret_cast<h4*>(out16 + (size_t)row * DD + c) = o;
        }
    }
}

// ---------------- launch ----------------
extern "C" void kernel_launch(void* const* d_in, const int* in_sizes, int n_in,
                              void* d_out, int out_size)
{
    const float* src  = (const float*)d_in[0];
    const float* Wq   = (const float*)d_in[1];  const float* bq  = (const float*)d_in[2];
    const float* Wk   = (const float*)d_in[3];  const float* bk  = (const float*)d_in[4];
    const float* Wv   = (const float*)d_in[5];  const float* bv  = (const float*)d_in[6];
    const float* mat  = (const float*)d_in[7];
    const float* Wo   = (const float*)d_in[8];  const float* bo  = (const float*)d_in[9];
    const float* ln1g = (const float*)d_in[10]; const float* ln1b = (const float*)d_in[11];
    const float* W1   = (const float*)d_in[12]; const float* b1  = (const float*)d_in[13];
    const float* W2   = (const float*)d_in[14]; const float* b2  = (const float*)d_in[15];
    const float* ln2g = (const float*)d_in[16]; const float* ln2b = (const float*)d_in[17];

    float* y_out = (float*)d_out;
    float* scores_out = y_out + (size_t)NT * DD;

    __half *src16, *q16, *k16, *v16, *ao16, *x16, *ff16, *wt;
    float *t, *x;
    cudaGetSymbolAddress((void**)&src16, g_src16);
    cudaGetSymbolAddress((void**)&q16,  g_q16);
    cudaGetSymbolAddress((void**)&k16,  g_k16);
    cudaGetSymbolAddress((void**)&v16,  g_v16);
    cudaGetSymbolAddress((void**)&ao16, g_ao16);
    cudaGetSymbolAddress((void**)&x16,  g_x16);
    cudaGetSymbolAddress((void**)&ff16, g_ff16);
    cudaGetSymbolAddress((void**)&wt,   g_wt16);
    cudaGetSymbolAddress((void**)&t,    g_t);
    cudaGetSymbolAddress((void**)&x,    g_x);

    cudaFuncSetAttribute(qkv_kernel,     cudaFuncAttributeMaxDynamicSharedMemorySize, SMEM_GEMM);
    cudaFuncSetAttribute(gemm_kernel<1>, cudaFuncAttributeMaxDynamicSharedMemorySize, SMEM_GEMM);
    cudaFuncSetAttribute(gemm_kernel<2>, cudaFuncAttributeMaxDynamicSharedMemorySize, SMEM_GEMM);
    cudaFuncSetAttribute(attn_kernel,    cudaFuncAttributeMaxDynamicSharedMemorySize, SMEM_ATTN);

    // ---- prep: src->fp16, weights transpose+fp16 ----
    cvt16_kernel<<<(NT*DD/4 + 255)/256, 256>>>(src, src16, NT*DD/4);
    dim3 tb(32, 8);
    transpose16_kernel<<<dim3(DD/32, DD/32), tb>>>(Wq, wt + WT_Q, DD, DD);
    transpose16_kernel<<<dim3(DD/32, DD/32), tb>>>(Wk, wt + WT_K, DD, DD);
    transpose16_kernel<<<dim3(DD/32, DD/32), tb>>>(Wv, wt + WT_V, DD, DD);
    transpose16_kernel<<<dim3(DD/32, DD/32), tb>>>(Wo, wt + WT_O, DD, DD);
    transpose16_kernel<<<dim3(DFF/32, DD/32), tb>>>(W1, wt + WT_1, DD, DFF);
    transpose16_kernel<<<dim3(DD/32, DFF/32), tb>>>(W2, wt + WT_2, DFF, DD);

    dim3 gqkv(DD / 128, NT / 128, 3);   // (4, 192, 3)
    dim3 g512(DD / 128, NT / 128);      // (4, 192)
    dim3 gff (DFF / 128, NT / 128);     // (16, 192)

    qkv_kernel<<<gqkv, 256, SMEM_GEMM>>>(src16, wt, bq, bk, bv, q16, k16, v16);
    attn_kernel<<<BB * HH, 256, SMEM_ATTN>>>(q16, k16, v16, mat, scores_out, ao16);
    gemm_kernel<2><<<g512, 256, SMEM_GEMM>>>(ao16, wt + WT_O, bo, src, t, DD, DD);
    ln_kernel<<<NT / 8, 256>>>(t, ln1g, ln1b, x, x16);
    gemm_kernel<1><<<gff, 256, SMEM_GEMM>>>(x16, wt + WT_1, b1, nullptr, ff16, DFF, DD);
    gemm_kernel<2><<<g512, 256, SMEM_GEMM>>>(ff16, wt + WT_2, b2, x, t, DD, DFF);
    ln_kernel<<<NT / 8, 256>>>(t, ln2g, ln2b, y_out, nullptr);
}

// round 8
// speedup vs baseline: 4.7778x; 1.0974x over previous
#include <cuda_runtime.h>
#include <cuda_fp16.h>
#include <math.h>
#include <stdint.h>

// ---------------- problem dims ----------------
#define BB 256
#define LL 96
#define DD 512
#define HH 8
#define HDIM 64
#define DFF 2048
#define NT (BB*LL)          // 24576 tokens
#define SCALE 0.125f
#define EPS_LN 1e-5f
#define LOG2E 1.4426950408889634f

// ---------------- scratch (no allocs allowed) ----------------
__device__ __align__(16) __half g_src16[NT*DD];
__device__ __align__(16) __half g_q16 [NT*DD];
__device__ __align__(16) __half g_k16 [NT*DD];
__device__ __align__(16) __half g_v16 [NT*DD];
__device__ __align__(16) __half g_ao16[NT*DD];
__device__ __align__(16) __half g_x16 [NT*DD];
__device__ __align__(16) __half g_ff16[NT*DFF];
__device__ float g_t [NT*DD];
__device__ float g_x [NT*DD];
__device__ __align__(16) __half g_wt16[4*DD*DD + 2*DD*DFF];   // transposed fp16 weights

// offsets into g_wt16 (halves)
#define WT_Q  0
#define WT_K  (DD*DD)
#define WT_V  (2*DD*DD)
#define WT_O  (3*DD*DD)
#define WT_1  (4*DD*DD)            // W1T [2048,512]
#define WT_2  (4*DD*DD + DD*DFF)   // W2T [512,2048]

struct h4 { __half2 a, b; };

// ---------------- helpers ----------------
__device__ __forceinline__ void cp_async16(uint32_t dst, const void* src) {
    asm volatile("cp.async.cg.shared.global [%0], [%1], 16;" :: "r"(dst), "l"(src));
}
__device__ __forceinline__ void cp_commit() { asm volatile("cp.async.commit_group;" ::: "memory"); }
__device__ __forceinline__ void cp_wait2()  { asm volatile("cp.async.wait_group 2;" ::: "memory"); }

__device__ __forceinline__ void mma_f16(float* c, const uint32_t* a, const uint32_t* b) {
    asm volatile(
        "mma.sync.aligned.m16n8k16.row.col.f32.f16.f16.f32 "
        "{%0,%1,%2,%3}, {%4,%5,%6,%7}, {%8,%9}, {%0,%1,%2,%3};\n"
        : "+f"(c[0]), "+f"(c[1]), "+f"(c[2]), "+f"(c[3])
        : "r"(a[0]), "r"(a[1]), "r"(a[2]), "r"(a[3]), "r"(b[0]), "r"(b[1]));
}

__device__ __forceinline__ uint32_t h2ex2(uint32_t x) {
    uint32_t r;
    asm("ex2.approx.f16x2 %0, %1;" : "=r"(r) : "r"(x));
    return r;
}

__device__ __forceinline__ float gelu_exact(float x) {
    return 0.5f * x * (1.f + erff(x * 0.70710678118654752f));
}

// ---------------- fp16 MMA GEMM, cp.async 4-stage (unchanged from R6) ----------------
#define STAGES 4
#define ROWB 80
#define A_ST (128*ROWB)
#define B_ST (128*ROWB)
#define SMEM_GEMM (STAGES*(A_ST+B_ST))  // 81920 B

// EPI: 0 = bias -> fp16 out; 1 = bias+gelu -> fp16 out; 2 = bias+residual -> fp32 out
template<int EPI>
__device__ __forceinline__ void gemm_body(
    const __half* __restrict__ A, const __half* __restrict__ Bt,
    const float* __restrict__ bias, const float* __restrict__ resid,
    void* __restrict__ Cout, int N, int K)
{
    extern __shared__ char smem[];
    const uint32_t smemA = (uint32_t)__cvta_generic_to_shared(smem);
    const uint32_t smemB = smemA + STAGES * A_ST;

    const int tid  = threadIdx.x;
    const int lane = tid & 31;
    const int wid  = tid >> 5;
    const int wm   = wid >> 2;
    const int wn   = wid & 3;
    const int lq   = lane & 3;
    const int lg   = lane >> 2;

    const __half* Ablk = A  + (size_t)blockIdx.y * 128 * K;
    const __half* Bblk = Bt + (size_t)blockIdx.x * 128 * K;

    const int ca_r0 = tid >> 2,         ca_c0 = tid & 3;
    const int ca_r1 = (tid + 256) >> 2, ca_c1 = (tid + 256) & 3;

    float acc[4][4][4];
    #pragma unroll
    for (int mt = 0; mt < 4; mt++)
        #pragma unroll
        for (int nt = 0; nt < 4; nt++)
            #pragma unroll
            for (int r = 0; r < 4; r++) acc[mt][nt][r] = 0.f;

    const int KT = K >> 5;

    auto load_tile = [&](int kt) {
        const int s = kt & (STAGES - 1);
        const int kof = kt << 5;
        cp_async16(smemA + s*A_ST + ca_r0*ROWB + ca_c0*16, Ablk + (size_t)ca_r0 * K + kof + ca_c0*8);
        cp_async16(smemA + s*A_ST + ca_r1*ROWB + ca_c1*16, Ablk + (size_t)ca_r1 * K + kof + ca_c1*8);
        cp_async16(smemB + s*B_ST + ca_r0*ROWB + ca_c0*16, Bblk + (size_t)ca_r0 * K + kof + ca_c0*8);
        cp_async16(smemB + s*B_ST + ca_r1*ROWB + ca_c1*16, Bblk + (size_t)ca_r1 * K + kof + ca_c1*8);
    };

    #pragma unroll
    for (int s = 0; s < STAGES - 1; s++) { load_tile(s); cp_commit(); }

    for (int kt = 0; kt < KT; kt++) {
        cp_wait2();
        __syncthreads();

        int nk = kt + STAGES - 1;
        if (nk < KT) load_tile(nk);
        cp_commit();

        const char* as = smem + (kt & (STAGES - 1)) * A_ST;
        const char* bs = smem + STAGES * A_ST + (kt & (STAGES - 1)) * B_ST;

        #pragma unroll
        for (int q0 = 0; q0 < 32; q0 += 16) {
            const int kb = 2 * (q0 + 2 * lq);
            uint32_t af[4][4], bf[4][2];
            #pragma unroll
            for (int mt = 0; mt < 4; mt++) {
                int m = wm * 64 + mt * 16 + lg;
                const char* p = as + m * ROWB + kb;
                af[mt][0] = *reinterpret_cast<const uint32_t*>(p);
                af[mt][1] = *reinterpret_cast<const uint32_t*>(p + 8 * ROWB);
                af[mt][2] = *reinterpret_cast<const uint32_t*>(p + 16);
                af[mt][3] = *reinterpret_cast<const uint32_t*>(p + 8 * ROWB + 16);
            }
            #pragma unroll
            for (int nt = 0; nt < 4; nt++) {
                int n = wn * 32 + nt * 8 + lg;
                const char* p = bs + n * ROWB + kb;
                bf[nt][0] = *reinterpret_cast<const uint32_t*>(p);
                bf[nt][1] = *reinterpret_cast<const uint32_t*>(p + 16);
            }
            #pragma unroll
            for (int mt = 0; mt < 4; mt++)
                #pragma unroll
                for (int nt = 0; nt < 4; nt++)
                    mma_f16(acc[mt][nt], af[mt], bf[nt]);
        }
    }

    #pragma unroll
    for (int mt = 0; mt < 4; mt++) {
        #pragma unroll
        for (int nt = 0; nt < 4; nt++) {
            int row = blockIdx.y * 128 + wm * 64 + mt * 16 + lg;
            int col = blockIdx.x * 128 + wn * 32 + nt * 8 + 2 * lq;
            float2 bv = *reinterpret_cast<const float2*>(bias + col);
            #pragma unroll
            for (int half_i = 0; half_i < 2; half_i++) {
                int r = row + half_i * 8;
                float ox = acc[mt][nt][half_i * 2 + 0] + bv.x;
                float oy = acc[mt][nt][half_i * 2 + 1] + bv.y;
                if (EPI == 1) { ox = gelu_exact(ox); oy = gelu_exact(oy); }
                if (EPI == 2) {
                    float2 rv = *reinterpret_cast<const float2*>(resid + (size_t)r * N + col);
                    ox += rv.x; oy += rv.y;
                    *reinterpret_cast<float2*>((float*)Cout + (size_t)r * N + col) = make_float2(ox, oy);
                } else {
                    *reinterpret_cast<__half2*>((__half*)Cout + (size_t)r * N + col) =
                        __floats2half2_rn(ox, oy);
                }
            }
        }
    }
}

__global__ void __launch_bounds__(256, 2) qkv_kernel(
    const __half* __restrict__ src16, const __half* __restrict__ wt,
    const float* __restrict__ bq, const float* __restrict__ bk, const float* __restrict__ bv,
    __half* __restrict__ q, __half* __restrict__ k, __half* __restrict__ v)
{
    const __half* Bt; const float* b; __half* out;
    if (blockIdx.z == 0)      { Bt = wt + WT_Q; b = bq; out = q; }
    else if (blockIdx.z == 1) { Bt = wt + WT_K; b = bk; out = k; }
    else                      { Bt = wt + WT_V; b = bv; out = v; }
    gemm_body<0>(src16, Bt, b, nullptr, out, DD, DD);
}

template<int EPI>
__global__ void __launch_bounds__(256, 2) gemm_kernel(
    const __half* __restrict__ A, const __half* __restrict__ Bt,
    const float* __restrict__ bias, const float* __restrict__ resid,
    void* __restrict__ C, int N, int K)
{
    gemm_body<EPI>(A, Bt, bias, resid, C, N, K);
}

// ---------------- weight transpose fp32[K,N] -> fp16[N,K] ----------------
__global__ void __launch_bounds__(256) transpose16_kernel(
    const float* __restrict__ in, __half* __restrict__ out, int K, int N)
{
    __shared__ float t[32][33];
    const int tx = threadIdx.x, ty = threadIdx.y;
    const int x0 = blockIdx.x * 32, y0 = blockIdx.y * 32;
    #pragma unroll
    for (int j = 0; j < 4; j++)
        t[ty + 8 * j][tx] = in[(size_t)(y0 + ty + 8 * j) * N + x0 + tx];
    __syncthreads();
    #pragma unroll
    for (int j = 0; j < 4; j++)
        out[(size_t)(x0 + ty + 8 * j) * K + y0 + tx] = __float2half(t[tx][ty + 8 * j]);
}

// ---------------- fp32 -> fp16 convert ----------------
__global__ void __launch_bounds__(256) cvt16_kernel(
    const float* __restrict__ in, __half* __restrict__ out, int n4)
{
    int i = blockIdx.x * 256 + threadIdx.x;
    if (i < n4) {
        float4 v = reinterpret_cast<const float4*>(in)[i];
        h4 o;
        o.a = __floats2half2_rn(v.x, v.y);
        o.b = __floats2half2_rn(v.z, v.w);
        reinterpret_cast<h4*>(out)[i] = o;
    }
}

// ---------------- fused attention per (b,h) — fp16 mma + half2 exp ----------------
// smem byte layout (dynamic):
//   phase 1: qs[96][72h] @0 (13824) | ks[96][72h] @13824 (13824) | vsT[64][104h] @27648 (13312) | ss[96][100f] @40960 (38400)
//   phase 2: ps[96][104h] @0 (19968, aliases qs/ks) | vsT, ss unchanged
#define AT_QS 0
#define AT_KS 13824
#define AT_VT 27648
#define AT_SS 40960
#define AT_PS 0
#define QROWB 144     // 72 halves
#define VROWB 208     // 104 halves
#define SROWF 100     // floats per ss row
#define SMEM_ATTN 79360

__global__ void __launch_bounds__(256, 2) attn_kernel(
    const __half* __restrict__ q, const __half* __restrict__ k, const __half* __restrict__ v,
    const float* __restrict__ matrix, float* __restrict__ scores_out, __half* __restrict__ ao)
{
    extern __shared__ char sm[];
    const int bh = blockIdx.x;
    const int b = bh / HH, h = bh % HH;
    const int tid = threadIdx.x;
    const int lane = tid & 31;
    const int wid  = tid >> 5;          // 0..7
    const int wm   = wid >> 2;          // 0..1
    const int wn   = wid & 3;           // 0..3
    const int lq   = lane & 3;
    const int lg   = lane >> 2;
    const size_t base = ((size_t)b * LL) * DD + h * HDIM;

    float* ss = reinterpret_cast<float*>(sm + AT_SS);

    // ---- load q,k (row-major fp16, padded rows) and v transposed ----
    for (int idx = tid; idx < LL * 32; idx += 256) {   // 96 rows x 32 half2
        int l = idx >> 5, d2 = idx & 31;
        __half2 qv = *reinterpret_cast<const __half2*>(q + base + (size_t)l * DD + 2 * d2);
        __half2 kv = *reinterpret_cast<const __half2*>(k + base + (size_t)l * DD + 2 * d2);
        __half2 vv = *reinterpret_cast<const __half2*>(v + base + (size_t)l * DD + 2 * d2);
        *reinterpret_cast<__half2*>(sm + AT_QS + l * QROWB + d2 * 4) = qv;
        *reinterpret_cast<__half2*>(sm + AT_KS + l * QROWB + d2 * 4) = kv;
        // transposed store: vsT[d][l]
        *reinterpret_cast<__half*>(sm + AT_VT + (2 * d2    ) * VROWB + l * 2) = __low2half(vv);
        *reinterpret_cast<__half*>(sm + AT_VT + (2 * d2 + 1) * VROWB + l * 2) = __high2half(vv);
    }
    __syncthreads();

    const float* mb  = matrix     + (size_t)bh * LL * LL;
    float*       sob = scores_out + (size_t)bh * LL * LL;

    // ---- S = Q K^T (mma), warp tile 48x24, then *matrix*SCALE -> sob + ss ----
    {
        float accS[3][3][4];
        #pragma unroll
        for (int mt = 0; mt < 3; mt++)
            #pragma unroll
            for (int nt = 0; nt < 3; nt++)
                #pragma unroll
                for (int r = 0; r < 4; r++) accS[mt][nt][r] = 0.f;

        #pragma unroll
        for (int q0 = 0; q0 < HDIM; q0 += 16) {
            const int kb = 2 * (q0 + 2 * lq);
            uint32_t af[3][4], bf[3][2];
            #pragma unroll
            for (int mt = 0; mt < 3; mt++) {
                const char* p = sm + AT_QS + (wm * 48 + mt * 16 + lg) * QROWB + kb;
                af[mt][0] = *reinterpret_cast<const uint32_t*>(p);
                af[mt][1] = *reinterpret_cast<const uint32_t*>(p + 8 * QROWB);
                af[mt][2] = *reinterpret_cast<const uint32_t*>(p + 16);
                af[mt][3] = *reinterpret_cast<const uint32_t*>(p + 8 * QROWB + 16);
            }
            #pragma unroll
            for (int nt = 0; nt < 3; nt++) {
                const char* p = sm + AT_KS + (wn * 24 + nt * 8 + lg) * QROWB + kb;
                bf[nt][0] = *reinterpret_cast<const uint32_t*>(p);
                bf[nt][1] = *reinterpret_cast<const uint32_t*>(p + 16);
            }
            #pragma unroll
            for (int mt = 0; mt < 3; mt++)
                #pragma unroll
                for (int nt = 0; nt < 3; nt++)
                    mma_f16(accS[mt][nt], af[mt], bf[nt]);
        }

        #pragma unroll
        for (int mt = 0; mt < 3; mt++) {
            #pragma unroll
            for (int nt = 0; nt < 3; nt++) {
                int row = wm * 48 + mt * 16 + lg;
                int col = wn * 24 + nt * 8 + 2 * lq;
                #pragma unroll
                for (int half_i = 0; half_i < 2; half_i++) {
                    int r = row + half_i * 8;
                    float2 mv = *reinterpret_cast<const float2*>(mb + (size_t)r * LL + col);
                    float sx = accS[mt][nt][half_i * 2 + 0] * mv.x * SCALE;
                    float sy = accS[mt][nt][half_i * 2 + 1] * mv.y * SCALE;
                    *reinterpret_cast<float2*>(sob + (size_t)r * LL + col) = make_float2(sx, sy);
                    ss[r * SROWF + col]     = sx;
                    ss[r * SROWF + col + 1] = sy;
                }
            }
        }
    }
    __syncthreads();

    // ---- softmax rows (warp per row-pair), half2 exp, P -> ps fp16 ----
    {
        #pragma unroll
        for (int rr = 0; rr < 6; rr++) {
            const int ra = wid + rr * 16;
            const int rb = ra + 8;
            float a0 = ss[ra * SROWF + lane];
            float a1 = ss[ra * SROWF + lane + 32];
            float a2 = ss[ra * SROWF + lane + 64];
            float b0 = ss[rb * SROWF + lane];
            float b1 = ss[rb * SROWF + lane + 32];
            float b2 = ss[rb * SROWF + lane + 64];
            float ma = fmaxf(fmaxf(a0, a1), a2);
            float mbv = fmaxf(fmaxf(b0, b1), b2);
            #pragma unroll
            for (int o = 16; o > 0; o >>= 1) {
                ma  = fmaxf(ma,  __shfl_xor_sync(0xffffffffu, ma,  o));
                mbv = fmaxf(mbv, __shfl_xor_sync(0xffffffffu, mbv, o));
            }
            __half2 e01 = __floats2half2_rn((a0 - ma) * LOG2E, (a1 - ma) * LOG2E);
            __half2 e2b0 = __floats2half2_rn((a2 - ma) * LOG2E, (b0 - mbv) * LOG2E);
            __half2 e12 = __floats2half2_rn((b1 - mbv) * LOG2E, (b2 - mbv) * LOG2E);
            uint32_t p01  = h2ex2(*reinterpret_cast<uint32_t*>(&e01));
            uint32_t p2b0 = h2ex2(*reinterpret_cast<uint32_t*>(&e2b0));
            uint32_t p12  = h2ex2(*reinterpret_cast<uint32_t*>(&e12));
            float2 f01  = __half22float2(*reinterpret_cast<__half2*>(&p01));
            float2 f2b0 = __half22float2(*reinterpret_cast<__half2*>(&p2b0));
            float2 f12  = __half22float2(*reinterpret_cast<__half2*>(&p12));
            float sa = f01.x + f01.y + f2b0.x;
            float sb = f2b0.y + f12.x + f12.y;
            #pragma unroll
            for (int o = 16; o > 0; o >>= 1) {
                sa += __shfl_xor_sync(0xffffffffu, sa, o);
                sb += __shfl_xor_sync(0xffffffffu, sb, o);
            }
            float inva = 1.f / sa, invb = 1.f / sb;
            __half2 ia2 = __floats2half2_rn(inva, inva);
            __half2 iab = __floats2half2_rn(inva, invb);
            __half2 ib2 = __floats2half2_rn(invb, invb);
            __half2 o01  = __hmul2(*reinterpret_cast<__half2*>(&p01),  ia2);
            __half2 o2b0 = __hmul2(*reinterpret_cast<__half2*>(&p2b0), iab);
            __half2 o12  = __hmul2(*reinterpret_cast<__half2*>(&p12),  ib2);
            *reinterpret_cast<__half*>(sm + AT_PS + ra * VROWB + (lane     ) * 2) = __low2half(o01);
            *reinterpret_cast<__half*>(sm + AT_PS + ra * VROWB + (lane + 32) * 2) = __high2half(o01);
            *reinterpret_cast<__half*>(sm + AT_PS + ra * VROWB + (lane + 64) * 2) = __low2half(o2b0);
            *reinterpret_cast<__half*>(sm + AT_PS + rb * VROWB + (lane     ) * 2) = __high2half(o2b0);
            *reinterpret_cast<__half*>(sm + AT_PS + rb * VROWB + (lane + 32) * 2) = __low2half(o12);
            *reinterpret_cast<__half*>(sm + AT_PS + rb * VROWB + (lane + 64) * 2) = __high2half(o12);
        }
    }
    __syncthreads();

    // ---- O = P V (mma), warp tile 48x16 over n=64 ----
    {
        float accO[3][2][4];
        #pragma unroll
        for (int mt = 0; mt < 3; mt++)
            #pragma unroll
            for (int nt = 0; nt < 2; nt++)
                #pragma unroll
                for (int r = 0; r < 4; r++) accO[mt][nt][r] = 0.f;

        #pragma unroll
        for (int k0 = 0; k0 < LL; k0 += 16) {
            const int kb = 2 * (k0 + 2 * lq);
            uint32_t af[3][4], bf[2][2];
            #pragma unroll
            for (int mt = 0; mt < 3; mt++) {
                const char* p = sm + AT_PS + (wm * 48 + mt * 16 + lg) * VROWB + kb;
                af[mt][0] = *reinterpret_cast<const uint32_t*>(p);
                af[mt][1] = *reinterpret_cast<const uint32_t*>(p + 8 * VROWB);
                af[mt][2] = *reinterpret_cast<const uint32_t*>(p + 16);
                af[mt][3] = *reinterpret_cast<const uint32_t*>(p + 8 * VROWB + 16);
            }
            #pragma unroll
            for (int nt = 0; nt < 2; nt++) {
                const char* p = sm + AT_VT + (wn * 16 + nt * 8 + lg) * VROWB + kb;
                bf[nt][0] = *reinterpret_cast<const uint32_t*>(p);
                bf[nt][1] = *reinterpret_cast<const uint32_t*>(p + 16);
            }
            #pragma unroll
            for (int mt = 0; mt < 3; mt++)
                #pragma unroll
                for (int nt = 0; nt < 2; nt++)
                    mma_f16(accO[mt][nt], af[mt], bf[nt]);
        }

        #pragma unroll
        for (int mt = 0; mt < 3; mt++) {
            #pragma unroll
            for (int nt = 0; nt < 2; nt++) {
                int row = wm * 48 + mt * 16 + lg;
                int col = wn * 16 + nt * 8 + 2 * lq;
                *reinterpret_cast<__half2*>(ao + base + (size_t)row * DD + col) =
                    __floats2half2_rn(accO[mt][nt][0], accO[mt][nt][1]);
                *reinterpret_cast<__half2*>(ao + base + (size_t)(row + 8) * DD + col) =
                    __floats2half2_rn(accO[mt][nt][2], accO[mt][nt][3]);
            }
        }
    }
}

// ---------------- LayerNorm over D=512, warp per row (optional fp16 dual-out) ----------------
__global__ void __launch_bounds__(256) ln_kernel(
    const float* __restrict__ x, const float* __restrict__ gw, const float* __restrict__ bw,
    float* __restrict__ out, __half* __restrict__ out16)
{
    const int row  = blockIdx.x * 8 + (threadIdx.x >> 5);
    const int lane = threadIdx.x & 31;
    const float* xr = x + (size_t)row * DD;
    float4 v[4];
    float s = 0.f, s2 = 0.f;
    #pragma unroll
    for (int t = 0; t < 4; t++) {
        v[t] = *reinterpret_cast<const float4*>(xr + (size_t)(t * 32 + lane) * 4);
        s  += v[t].x + v[t].y + v[t].z + v[t].w;
        s2 += v[t].x * v[t].x + v[t].y * v[t].y + v[t].z * v[t].z + v[t].w * v[t].w;
    }
    #pragma unroll
    for (int o = 16; o > 0; o >>= 1) {
        s  += __shfl_xor_sync(0xffffffffu, s,  o);
        s2 += __shfl_xor_sync(0xffffffffu, s2, o);
    }
    const float mean = s * (1.f / DD);
    const float var  = s2 * (1.f / DD) - mean * mean;
    const float rstd = rsqrtf(var + EPS_LN);
    float* orow = out + (size_t)row * DD;
    #pragma unroll
    for (int t = 0; t < 4; t++) {
        int c = (t * 32 + lane) * 4;
        float4 gv = *reinterpret_cast<const float4*>(gw + c);
        float4 bv = *reinterpret_cast<const float4*>(bw + c);
        float4 r;
        r.x = (v[t].x - mean) * rstd * gv.x + bv.x;
        r.y = (v[t].y - mean) * rstd * gv.y + bv.y;
        r.z = (v[t].z - mean) * rstd * gv.z + bv.z;
        r.w = (v[t].w - mean) * rstd * gv.w + bv.w;
        *reinterpret_cast<float4*>(orow + c) = r;
        if (out16) {
            h4 o;
            o.a = __floats2half2_rn(r.x, r.y);
            o.b = __floats2half2_rn(r.z, r.w);
            *reinterpret_cast<h4*>(out16 + (size_t)row * DD + c) = o;
        }
    }
}

// ---------------- launch ----------------
extern "C" void kernel_launch(void* const* d_in, const int* in_sizes, int n_in,
                              void* d_out, int out_size)
{
    const float* src  = (const float*)d_in[0];
    const float* Wq   = (const float*)d_in[1];  const float* bq  = (const float*)d_in[2];
    const float* Wk   = (const float*)d_in[3];  const float* bk  = (const float*)d_in[4];
    const float* Wv   = (const float*)d_in[5];  const float* bv  = (const float*)d_in[6];
    const float* mat  = (const float*)d_in[7];
    const float* Wo   = (const float*)d_in[8];  const float* bo  = (const float*)d_in[9];
    const float* ln1g = (const float*)d_in[10]; const float* ln1b = (const float*)d_in[11];
    const float* W1   = (const float*)d_in[12]; const float* b1  = (const float*)d_in[13];
    const float* W2   = (const float*)d_in[14]; const float* b2  = (const float*)d_in[15];
    const float* ln2g = (const float*)d_in[16]; const float* ln2b = (const float*)d_in[17];

    float* y_out = (float*)d_out;
    float* scores_out = y_out + (size_t)NT * DD;

    __half *src16, *q16, *k16, *v16, *ao16, *x16, *ff16, *wt;
    float *t, *x;
    cudaGetSymbolAddress((void**)&src16, g_src16);
    cudaGetSymbolAddress((void**)&q16,  g_q16);
    cudaGetSymbolAddress((void**)&k16,  g_k16);
    cudaGetSymbolAddress((void**)&v16,  g_v16);
    cudaGetSymbolAddress((void**)&ao16, g_ao16);
    cudaGetSymbolAddress((void**)&x16,  g_x16);
    cudaGetSymbolAddress((void**)&ff16, g_ff16);
    cudaGetSymbolAddress((void**)&wt,   g_wt16);
    cudaGetSymbolAddress((void**)&t,    g_t);
    cudaGetSymbolAddress((void**)&x,    g_x);

    cudaFuncSetAttribute(qkv_kernel,     cudaFuncAttributeMaxDynamicSharedMemorySize, SMEM_GEMM);
    cudaFuncSetAttribute(gemm_kernel<1>, cudaFuncAttributeMaxDynamicSharedMemorySize, SMEM_GEMM);
    cudaFuncSetAttribute(gemm_kernel<2>, cudaFuncAttributeMaxDynamicSharedMemorySize, SMEM_GEMM);
    cudaFuncSetAttribute(attn_kernel,    cudaFuncAttributeMaxDynamicSharedMemorySize, SMEM_ATTN);

    // ---- prep: src->fp16, weights transpose+fp16 ----
    cvt16_kernel<<<(NT*DD/4 + 255)/256, 256>>>(src, src16, NT*DD/4);
    dim3 tb(32, 8);
    transpose16_kernel<<<dim3(DD/32, DD/32), tb>>>(Wq, wt + WT_Q, DD, DD);
    transpose16_kernel<<<dim3(DD/32, DD/32), tb>>>(Wk, wt + WT_K, DD, DD);
    transpose16_kernel<<<dim3(DD/32, DD/32), tb>>>(Wv, wt + WT_V, DD, DD);
    transpose16_kernel<<<dim3(DD/32, DD/32), tb>>>(Wo, wt + WT_O, DD, DD);
    transpose16_kernel<<<dim3(DFF/32, DD/32), tb>>>(W1, wt + WT_1, DD, DFF);
    transpose16_kernel<<<dim3(DD/32, DFF/32), tb>>>(W2, wt + WT_2, DFF, DD);

    dim3 gqkv(DD / 128, NT / 128, 3);
    dim3 g512(DD / 128, NT / 128);
    dim3 gff (DFF / 128, NT / 128);

    qkv_kernel<<<gqkv, 256, SMEM_GEMM>>>(src16, wt, bq, bk, bv, q16, k16, v16);
    attn_kernel<<<BB * HH, 256, SMEM_ATTN>>>(q16, k16, v16, mat, scores_out, ao16);
    gemm_kernel<2><<<g512, 256, SMEM_GEMM>>>(ao16, wt + WT_O, bo, src, t, DD, DD);
    ln_kernel<<<NT / 8, 256>>>(t, ln1g, ln1b, x, x16);
    gemm_kernel<1><<<gff, 256, SMEM_GEMM>>>(x16, wt + WT_1, b1, nullptr, ff16, DFF, DD);
    gemm_kernel<2><<<g512, 256, SMEM_GEMM>>>(ff16, wt + WT_2, b2, x, t, DD, DFF);
    ln_kernel<<<NT / 8, 256>>>(t, ln2g, ln2b, y_out, nullptr);
}

// round 9
// speedup vs baseline: 5.1655x; 1.0812x over previous
#include <cuda_runtime.h>
#include <cuda_fp16.h>
#include <math.h>
#include <stdint.h>

// ---------------- problem dims ----------------
#define BB 256
#define LL 96
#define DD 512
#define HH 8
#define HDIM 64
#define DFF 2048
#define NT (BB*LL)          // 24576 tokens
#define SCALE 0.125f
#define EPS_LN 1e-5f
#define LOG2E 1.4426950408889634f

// ---------------- scratch (no allocs allowed) ----------------
__device__ __align__(16) __half g_src16[NT*DD];
__device__ __align__(16) __half g_q16 [NT*DD];
__device__ __align__(16) __half g_k16 [NT*DD];
__device__ __align__(16) __half g_v16 [NT*DD];
__device__ __align__(16) __half g_ao16[NT*DD];
__device__ __align__(16) __half g_x16 [NT*DD];
__device__ __align__(16) __half g_ff16[NT*DFF];
__device__ float g_t [NT*DD];
__device__ float g_x [NT*DD];
__device__ __align__(16) __half g_wt16[4*DD*DD + 2*DD*DFF];   // transposed fp16 weights

// offsets into g_wt16 (halves)
#define WT_Q  0
#define WT_K  (DD*DD)
#define WT_V  (2*DD*DD)
#define WT_O  (3*DD*DD)
#define WT_1  (4*DD*DD)            // W1T [2048,512]
#define WT_2  (4*DD*DD + DD*DFF)   // W2T [512,2048]

struct h4 { __half2 a, b; };

// ---------------- helpers ----------------
__device__ __forceinline__ void cp_async16(uint32_t dst, const void* src) {
    asm volatile("cp.async.cg.shared.global [%0], [%1], 16;" :: "r"(dst), "l"(src));
}
__device__ __forceinline__ void cp_commit() { asm volatile("cp.async.commit_group;" ::: "memory"); }
__device__ __forceinline__ void cp_wait2()  { asm volatile("cp.async.wait_group 2;" ::: "memory"); }

__device__ __forceinline__ void mma_f16(float* c, const uint32_t* a, const uint32_t* b) {
    asm volatile(
        "mma.sync.aligned.m16n8k16.row.col.f32.f16.f16.f32 "
        "{%0,%1,%2,%3}, {%4,%5,%6,%7}, {%8,%9}, {%0,%1,%2,%3};\n"
        : "+f"(c[0]), "+f"(c[1]), "+f"(c[2]), "+f"(c[3])
        : "r"(a[0]), "r"(a[1]), "r"(a[2]), "r"(a[3]), "r"(b[0]), "r"(b[1]));
}

__device__ __forceinline__ void ldsm_x4(uint32_t* r, uint32_t addr) {
    asm volatile("ldmatrix.sync.aligned.m8n8.x4.shared.b16 {%0,%1,%2,%3}, [%4];"
        : "=r"(r[0]), "=r"(r[1]), "=r"(r[2]), "=r"(r[3]) : "r"(addr));
}
__device__ __forceinline__ void ldsm_x2(uint32_t* r, uint32_t addr) {
    asm volatile("ldmatrix.sync.aligned.m8n8.x2.shared.b16 {%0,%1}, [%2];"
        : "=r"(r[0]), "=r"(r[1]) : "r"(addr));
}

__device__ __forceinline__ uint32_t h2ex2(uint32_t x) {
    uint32_t r;
    asm("ex2.approx.f16x2 %0, %1;" : "=r"(r) : "r"(x));
    return r;
}

__device__ __forceinline__ float gelu_exact(float x) {
    return 0.5f * x * (1.f + erff(x * 0.70710678118654752f));
}

// ---------------- fp16 MMA GEMM, cp.async 4-stage + ldmatrix ----------------
#define STAGES 4
#define ROWB 80
#define A_ST (128*ROWB)
#define B_ST (128*ROWB)
#define SMEM_GEMM (STAGES*(A_ST+B_ST))  // 81920 B

// EPI: 0 = bias -> fp16 out; 1 = bias+gelu -> fp16 out; 2 = bias+residual -> fp32 out
template<int EPI>
__device__ __forceinline__ void gemm_body(
    const __half* __restrict__ A, const __half* __restrict__ Bt,
    const float* __restrict__ bias, const float* __restrict__ resid,
    void* __restrict__ Cout, int N, int K)
{
    extern __shared__ char smem[];
    const uint32_t smemA = (uint32_t)__cvta_generic_to_shared(smem);
    const uint32_t smemB = smemA + STAGES * A_ST;

    const int tid  = threadIdx.x;
    const int lane = tid & 31;
    const int wid  = tid >> 5;
    const int wm   = wid >> 2;
    const int wn   = wid & 3;
    const int lq   = lane & 3;
    const int lg   = lane >> 2;

    // ldmatrix lane addressing
    const int a_row  = (lane & 7) | (((lane >> 3) & 1) << 3);   // 0..15
    const int a_c16  = (lane >> 4) << 4;                         // 0 or 16 bytes
    const int b_row  = lane & 7;
    const int b_c16  = ((lane >> 3) & 1) << 4;

    const __half* Ablk = A  + (size_t)blockIdx.y * 128 * K;
    const __half* Bblk = Bt + (size_t)blockIdx.x * 128 * K;

    const int ca_r0 = tid >> 2,         ca_c0 = tid & 3;
    const int ca_r1 = (tid + 256) >> 2, ca_c1 = (tid + 256) & 3;

    float acc[4][4][4];
    #pragma unroll
    for (int mt = 0; mt < 4; mt++)
        #pragma unroll
        for (int nt = 0; nt < 4; nt++)
            #pragma unroll
            for (int r = 0; r < 4; r++) acc[mt][nt][r] = 0.f;

    const int KT = K >> 5;

    auto load_tile = [&](int kt) {
        const int s = kt & (STAGES - 1);
        const int kof = kt << 5;
        cp_async16(smemA + s*A_ST + ca_r0*ROWB + ca_c0*16, Ablk + (size_t)ca_r0 * K + kof + ca_c0*8);
        cp_async16(smemA + s*A_ST + ca_r1*ROWB + ca_c1*16, Ablk + (size_t)ca_r1 * K + kof + ca_c1*8);
        cp_async16(smemB + s*B_ST + ca_r0*ROWB + ca_c0*16, Bblk + (size_t)ca_r0 * K + kof + ca_c0*8);
        cp_async16(smemB + s*B_ST + ca_r1*ROWB + ca_c1*16, Bblk + (size_t)ca_r1 * K + kof + ca_c1*8);
    };

    #pragma unroll
    for (int s = 0; s < STAGES - 1; s++) { load_tile(s); cp_commit(); }

    // per-thread ldmatrix base addresses (tile-local)
    const uint32_t a_lane_base = smemA + (wm * 64 + a_row) * ROWB + a_c16;
    const uint32_t b_lane_base = smemB + (wn * 32 + b_row) * ROWB + b_c16;

    for (int kt = 0; kt < KT; kt++) {
        cp_wait2();
        __syncthreads();

        int nk = kt + STAGES - 1;
        if (nk < KT) load_tile(nk);
        cp_commit();

        const int s = kt & (STAGES - 1);
        const uint32_t abase = a_lane_base + s * A_ST;
        const uint32_t bbase = b_lane_base + s * B_ST;

        #pragma unroll
        for (int q0 = 0; q0 < 32; q0 += 16) {
            const int kb = 2 * q0;
            uint32_t af[4][4], bf[4][2];
            #pragma unroll
            for (int mt = 0; mt < 4; mt++)
                ldsm_x4(af[mt], abase + mt * 16 * ROWB + kb);
            #pragma unroll
            for (int nt = 0; nt < 4; nt++)
                ldsm_x2(bf[nt], bbase + nt * 8 * ROWB + kb);
            #pragma unroll
            for (int mt = 0; mt < 4; mt++)
                #pragma unroll
                for (int nt = 0; nt < 4; nt++)
                    mma_f16(acc[mt][nt], af[mt], bf[nt]);
        }
    }

    #pragma unroll
    for (int mt = 0; mt < 4; mt++) {
        #pragma unroll
        for (int nt = 0; nt < 4; nt++) {
            int row = blockIdx.y * 128 + wm * 64 + mt * 16 + lg;
            int col = blockIdx.x * 128 + wn * 32 + nt * 8 + 2 * lq;
            float2 bv = *reinterpret_cast<const float2*>(bias + col);
            #pragma unroll
            for (int half_i = 0; half_i < 2; half_i++) {
                int r = row + half_i * 8;
                float ox = acc[mt][nt][half_i * 2 + 0] + bv.x;
                float oy = acc[mt][nt][half_i * 2 + 1] + bv.y;
                if (EPI == 1) { ox = gelu_exact(ox); oy = gelu_exact(oy); }
                if (EPI == 2) {
                    float2 rv = *reinterpret_cast<const float2*>(resid + (size_t)r * N + col);
                    ox += rv.x; oy += rv.y;
                    *reinterpret_cast<float2*>((float*)Cout + (size_t)r * N + col) = make_float2(ox, oy);
                } else {
                    *reinterpret_cast<__half2*>((__half*)Cout + (size_t)r * N + col) =
                        __floats2half2_rn(ox, oy);
                }
            }
        }
    }
}

__global__ void __launch_bounds__(256, 2) qkv_kernel(
    const __half* __restrict__ src16, const __half* __restrict__ wt,
    const float* __restrict__ bq, const float* __restrict__ bk, const float* __restrict__ bv,
    __half* __restrict__ q, __half* __restrict__ k, __half* __restrict__ v)
{
    const __half* Bt; const float* b; __half* out;
    if (blockIdx.z == 0)      { Bt = wt + WT_Q; b = bq; out = q; }
    else if (blockIdx.z == 1) { Bt = wt + WT_K; b = bk; out = k; }
    else                      { Bt = wt + WT_V; b = bv; out = v; }
    gemm_body<0>(src16, Bt, b, nullptr, out, DD, DD);
}

template<int EPI>
__global__ void __launch_bounds__(256, 2) gemm_kernel(
    const __half* __restrict__ A, const __half* __restrict__ Bt,
    const float* __restrict__ bias, const float* __restrict__ resid,
    void* __restrict__ C, int N, int K)
{
    gemm_body<EPI>(A, Bt, bias, resid, C, N, K);
}

// ---------------- weight transpose fp32[K,N] -> fp16[N,K] ----------------
// batched over z for the four D x D weights
__global__ void __launch_bounds__(256) transpose4_kernel(
    const float* __restrict__ w0, const float* __restrict__ w1,
    const float* __restrict__ w2, const float* __restrict__ w3,
    __half* __restrict__ out)   // out + z*DD*DD
{
    __shared__ float t[32][33];
    const float* in = (blockIdx.z == 0) ? w0 : (blockIdx.z == 1) ? w1 : (blockIdx.z == 2) ? w2 : w3;
    __half* o = out + (size_t)blockIdx.z * DD * DD;
    const int tx = threadIdx.x, ty = threadIdx.y;
    const int x0 = blockIdx.x * 32, y0 = blockIdx.y * 32;
    #pragma unroll
    for (int j = 0; j < 4; j++)
        t[ty + 8 * j][tx] = in[(size_t)(y0 + ty + 8 * j) * DD + x0 + tx];
    __syncthreads();
    #pragma unroll
    for (int j = 0; j < 4; j++)
        o[(size_t)(x0 + ty + 8 * j) * DD + y0 + tx] = __float2half(t[tx][ty + 8 * j]);
}

__global__ void __launch_bounds__(256) transpose16_kernel(
    const float* __restrict__ in, __half* __restrict__ out, int K, int N)
{
    __shared__ float t[32][33];
    const int tx = threadIdx.x, ty = threadIdx.y;
    const int x0 = blockIdx.x * 32, y0 = blockIdx.y * 32;
    #pragma unroll
    for (int j = 0; j < 4; j++)
        t[ty + 8 * j][tx] = in[(size_t)(y0 + ty + 8 * j) * N + x0 + tx];
    __syncthreads();
    #pragma unroll
    for (int j = 0; j < 4; j++)
        out[(size_t)(x0 + ty + 8 * j) * K + y0 + tx] = __float2half(t[tx][ty + 8 * j]);
}

// ---------------- fp32 -> fp16 convert ----------------
__global__ void __launch_bounds__(256) cvt16_kernel(
    const float* __restrict__ in, __half* __restrict__ out, int n4)
{
    int i = blockIdx.x * 256 + threadIdx.x;
    if (i < n4) {
        float4 v = reinterpret_cast<const float4*>(in)[i];
        h4 o;
        o.a = __floats2half2_rn(v.x, v.y);
        o.b = __floats2half2_rn(v.z, v.w);
        reinterpret_cast<h4*>(out)[i] = o;
    }
}

// ---------------- fused attention per (b,h) — fp16 mma + half2 exp ----------------
#define AT_QS 0
#define AT_KS 13824
#define AT_VT 27648
#define AT_SS 40960
#define AT_PS 0
#define QROWB 144     // 72 halves
#define VROWB 208     // 104 halves
#define SROWF 100     // floats per ss row
#define SMEM_ATTN 79360

__global__ void __launch_bounds__(256, 2) attn_kernel(
    const __half* __restrict__ q, const __half* __restrict__ k, const __half* __restrict__ v,
    const float* __restrict__ matrix, float* __restrict__ scores_out, __half* __restrict__ ao)
{
    extern __shared__ char sm[];
    const int bh = blockIdx.x;
    const int b = bh / HH, h = bh % HH;
    const int tid = threadIdx.x;
    const int lane = tid & 31;
    const int wid  = tid >> 5;
    const int wm   = wid >> 2;
    const int wn   = wid & 3;
    const int lq   = lane & 3;
    const int lg   = lane >> 2;
    const size_t base = ((size_t)b * LL) * DD + h * HDIM;

    float* ss = reinterpret_cast<float*>(sm + AT_SS);

    for (int idx = tid; idx < LL * 32; idx += 256) {
        int l = idx >> 5, d2 = idx & 31;
        __half2 qv = *reinterpret_cast<const __half2*>(q + base + (size_t)l * DD + 2 * d2);
        __half2 kv = *reinterpret_cast<const __half2*>(k + base + (size_t)l * DD + 2 * d2);
        __half2 vv = *reinterpret_cast<const __half2*>(v + base + (size_t)l * DD + 2 * d2);
        *reinterpret_cast<__half2*>(sm + AT_QS + l * QROWB + d2 * 4) = qv;
        *reinterpret_cast<__half2*>(sm + AT_KS + l * QROWB + d2 * 4) = kv;
        *reinterpret_cast<__half*>(sm + AT_VT + (2 * d2    ) * VROWB + l * 2) = __low2half(vv);
        *reinterpret_cast<__half*>(sm + AT_VT + (2 * d2 + 1) * VROWB + l * 2) = __high2half(vv);
    }
    __syncthreads();

    const float* mb  = matrix     + (size_t)bh * LL * LL;
    float*       sob = scores_out + (size_t)bh * LL * LL;

    {
        float accS[3][3][4];
        #pragma unroll
        for (int mt = 0; mt < 3; mt++)
            #pragma unroll
            for (int nt = 0; nt < 3; nt++)
                #pragma unroll
                for (int r = 0; r < 4; r++) accS[mt][nt][r] = 0.f;

        #pragma unroll
        for (int q0 = 0; q0 < HDIM; q0 += 16) {
            const int kb = 2 * (q0 + 2 * lq);
            uint32_t af[3][4], bf[3][2];
            #pragma unroll
            for (int mt = 0; mt < 3; mt++) {
                const char* p = sm + AT_QS + (wm * 48 + mt * 16 + lg) * QROWB + kb;
                af[mt][0] = *reinterpret_cast<const uint32_t*>(p);
                af[mt][1] = *reinterpret_cast<const uint32_t*>(p + 8 * QROWB);
                af[mt][2] = *reinterpret_cast<const uint32_t*>(p + 16);
                af[mt][3] = *reinterpret_cast<const uint32_t*>(p + 8 * QROWB + 16);
            }
            #pragma unroll
            for (int nt = 0; nt < 3; nt++) {
                const char* p = sm + AT_KS + (wn * 24 + nt * 8 + lg) * QROWB + kb;
                bf[nt][0] = *reinterpret_cast<const uint32_t*>(p);
                bf[nt][1] = *reinterpret_cast<const uint32_t*>(p + 16);
            }
            #pragma unroll
            for (int mt = 0; mt < 3; mt++)
                #pragma unroll
                for (int nt = 0; nt < 3; nt++)
                    mma_f16(accS[mt][nt], af[mt], bf[nt]);
        }

        #pragma unroll
        for (int mt = 0; mt < 3; mt++) {
            #pragma unroll
            for (int nt = 0; nt < 3; nt++) {
                int row = wm * 48 + mt * 16 + lg;
                int col = wn * 24 + nt * 8 + 2 * lq;
                #pragma unroll
                for (int half_i = 0; half_i < 2; half_i++) {
                    int r = row + half_i * 8;
                    float2 mv = *reinterpret_cast<const float2*>(mb + (size_t)r * LL + col);
                    float sx = accS[mt][nt][half_i * 2 + 0] * mv.x * SCALE;
                    float sy = accS[mt][nt][half_i * 2 + 1] * mv.y * SCALE;
                    *reinterpret_cast<float2*>(sob + (size_t)r * LL + col) = make_float2(sx, sy);
                    ss[r * SROWF + col]     = sx;
                    ss[r * SROWF + col + 1] = sy;
                }
            }
        }
    }
    __syncthreads();

    {
        #pragma unroll
        for (int rr = 0; rr < 6; rr++) {
            const int ra = wid + rr * 16;
            const int rb = ra + 8;
            float a0 = ss[ra * SROWF + lane];
            float a1 = ss[ra * SROWF + lane + 32];
            float a2 = ss[ra * SROWF + lane + 64];
            float b0 = ss[rb * SROWF + lane];
            float b1 = ss[rb * SROWF + lane + 32];
            float b2 = ss[rb * SROWF + lane + 64];
            float ma = fmaxf(fmaxf(a0, a1), a2);
            float mbv = fmaxf(fmaxf(b0, b1), b2);
            #pragma unroll
            for (int o = 16; o > 0; o >>= 1) {
                ma  = fmaxf(ma,  __shfl_xor_sync(0xffffffffu, ma,  o));
                mbv = fmaxf(mbv, __shfl_xor_sync(0xffffffffu, mbv, o));
            }
            __half2 e01 = __floats2half2_rn((a0 - ma) * LOG2E, (a1 - ma) * LOG2E);
            __half2 e2b0 = __floats2half2_rn((a2 - ma) * LOG2E, (b0 - mbv) * LOG2E);
            __half2 e12 = __floats2half2_rn((b1 - mbv) * LOG2E, (b2 - mbv) * LOG2E);
            uint32_t p01  = h2ex2(*reinterpret_cast<uint32_t*>(&e01));
            uint32_t p2b0 = h2ex2(*reinterpret_cast<uint32_t*>(&e2b0));
            uint32_t p12  = h2ex2(*reinterpret_cast<uint32_t*>(&e12));
            float2 f01  = __half22float2(*reinterpret_cast<__half2*>(&p01));
            float2 f2b0 = __half22float2(*reinterpret_cast<__half2*>(&p2b0));
            float2 f12  = __half22float2(*reinterpret_cast<__half2*>(&p12));
            float sa = f01.x + f01.y + f2b0.x;
            float sb = f2b0.y + f12.x + f12.y;
            #pragma unroll
            for (int o = 16; o > 0; o >>= 1) {
                sa += __shfl_xor_sync(0xffffffffu, sa, o);
                sb += __shfl_xor_sync(0xffffffffu, sb, o);
            }
            float inva = 1.f / sa, invb = 1.f / sb;
            __half2 ia2 = __floats2half2_rn(inva, inva);
            __half2 iab = __floats2half2_rn(inva, invb);
            __half2 ib2 = __floats2half2_rn(invb, invb);
            __half2 o01  = __hmul2(*reinterpret_cast<__half2*>(&p01),  ia2);
            __half2 o2b0 = __hmul2(*reinterpret_cast<__half2*>(&p2b0), iab);
            __half2 o12  = __hmul2(*reinterpret_cast<__half2*>(&p12),  ib2);
            *reinterpret_cast<__half*>(sm + AT_PS + ra * VROWB + (lane     ) * 2) = __low2half(o01);
            *reinterpret_cast<__half*>(sm + AT_PS + ra * VROWB + (lane + 32) * 2) = __high2half(o01);
            *reinterpret_cast<__half*>(sm + AT_PS + ra * VROWB + (lane + 64) * 2) = __low2half(o2b0);
            *reinterpret_cast<__half*>(sm + AT_PS + rb * VROWB + (lane     ) * 2) = __high2half(o2b0);
            *reinterpret_cast<__half*>(sm + AT_PS + rb * VROWB + (lane + 32) * 2) = __low2half(o12);
            *reinterpret_cast<__half*>(sm + AT_PS + rb * VROWB + (lane + 64) * 2) = __high2half(o12);
        }
    }
    __syncthreads();

    {
        float accO[3][2][4];
        #pragma unroll
        for (int mt = 0; mt < 3; mt++)
            #pragma unroll
            for (int nt = 0; nt < 2; nt++)
                #pragma unroll
                for (int r = 0; r < 4; r++) accO[mt][nt][r] = 0.f;

        #pragma unroll
        for (int k0 = 0; k0 < LL; k0 += 16) {
            const int kb = 2 * (k0 + 2 * lq);
            uint32_t af[3][4], bf[2][2];
            #pragma unroll
            for (int mt = 0; mt < 3; mt++) {
                const char* p = sm + AT_PS + (wm * 48 + mt * 16 + lg) * VROWB + kb;
                af[mt][0] = *reinterpret_cast<const uint32_t*>(p);
                af[mt][1] = *reinterpret_cast<const uint32_t*>(p + 8 * VROWB);
                af[mt][2] = *reinterpret_cast<const uint32_t*>(p + 16);
                af[mt][3] = *reinterpret_cast<const uint32_t*>(p + 8 * VROWB + 16);
            }
            #pragma unroll
            for (int nt = 0; nt < 2; nt++) {
                const char* p = sm + AT_VT + (wn * 16 + nt * 8 + lg) * VROWB + kb;
                bf[nt][0] = *reinterpret_cast<const uint32_t*>(p);
                bf[nt][1] = *reinterpret_cast<const uint32_t*>(p + 16);
            }
            #pragma unroll
            for (int mt = 0; mt < 3; mt++)
                #pragma unroll
                for (int nt = 0; nt < 2; nt++)
                    mma_f16(accO[mt][nt], af[mt], bf[nt]);
        }

        #pragma unroll
        for (int mt = 0; mt < 3; mt++) {
            #pragma unroll
            for (int nt = 0; nt < 2; nt++) {
                int row = wm * 48 + mt * 16 + lg;
                int col = wn * 16 + nt * 8 + 2 * lq;
                *reinterpret_cast<__half2*>(ao + base + (size_t)row * DD + col) =
                    __floats2half2_rn(accO[mt][nt][0], accO[mt][nt][1]);
                *reinterpret_cast<__half2*>(ao + base + (size_t)(row + 8) * DD + col) =
                    __floats2half2_rn(accO[mt][nt][2], accO[mt][nt][3]);
            }
        }
    }
}

// ---------------- LayerNorm over D=512, warp per row (optional fp16 dual-out) ----------------
__global__ void __launch_bounds__(256) ln_kernel(
    const float* __restrict__ x, const float* __restrict__ gw, const float* __restrict__ bw,
    float* __restrict__ out, __half* __restrict__ out16)
{
    const int row  = blockIdx.x * 8 + (threadIdx.x >> 5);
    const int lane = threadIdx.x & 31;
    const float* xr = x + (size_t)row * DD;
    float4 v[4];
    float s = 0.f, s2 = 0.f;
    #pragma unroll
    for (int t = 0; t < 4; t++) {
        v[t] = *reinterpret_cast<const float4*>(xr + (size_t)(t * 32 + lane) * 4);
        s  += v[t].x + v[t].y + v[t].z + v[t].w;
        s2 += v[t].x * v[t].x + v[t].y * v[t].y + v[t].z * v[t].z + v[t].w * v[t].w;
    }
    #pragma unroll
    for (int o = 16; o > 0; o >>= 1) {
        s  += __shfl_xor_sync(0xffffffffu, s,  o);
        s2 += __shfl_xor_sync(0xffffffffu, s2, o);
    }
    const float mean = s * (1.f / DD);
    const float var  = s2 * (1.f / DD) - mean * mean;
    const float rstd = rsqrtf(var + EPS_LN);
    float* orow = out + (size_t)row * DD;
    #pragma unroll
    for (int t = 0; t < 4; t++) {
        int c = (t * 32 + lane) * 4;
        float4 gv = *reinterpret_cast<const float4*>(gw + c);
        float4 bv = *reinterpret_cast<const float4*>(bw + c);
        float4 r;
        r.x = (v[t].x - mean) * rstd * gv.x + bv.x;
        r.y = (v[t].y - mean) * rstd * gv.y + bv.y;
        r.z = (v[t].z - mean) * rstd * gv.z + bv.z;
        r.w = (v[t].w - mean) * rstd * gv.w + bv.w;
        *reinterpret_cast<float4*>(orow + c) = r;
        if (out16) {
            h4 o;
            o.a = __floats2half2_rn(r.x, r.y);
            o.b = __floats2half2_rn(r.z, r.w);
            *reinterpret_cast<h4*>(out16 + (size_t)row * DD + c) = o;
        }
    }
}

// ---------------- launch ----------------
extern "C" void kernel_launch(void* const* d_in, const int* in_sizes, int n_in,
                              void* d_out, int out_size)
{
    const float* src  = (const float*)d_in[0];
    const float* Wq   = (const float*)d_in[1];  const float* bq  = (const float*)d_in[2];
    const float* Wk   = (const float*)d_in[3];  const float* bk  = (const float*)d_in[4];
    const float* Wv   = (const float*)d_in[5];  const float* bv  = (const float*)d_in[6];
    const float* mat  = (const float*)d_in[7];
    const float* Wo   = (const float*)d_in[8];  const float* bo  = (const float*)d_in[9];
    const float* ln1g = (const float*)d_in[10]; const float* ln1b = (const float*)d_in[11];
    const float* W1   = (const float*)d_in[12]; const float* b1  = (const float*)d_in[13];
    const float* W2   = (const float*)d_in[14]; const float* b2  = (const float*)d_in[15];
    const float* ln2g = (const float*)d_in[16]; const float* ln2b = (const float*)d_in[17];

    float* y_out = (float*)d_out;
    float* scores_out = y_out + (size_t)NT * DD;

    __half *src16, *q16, *k16, *v16, *ao16, *x16, *ff16, *wt;
    float *t, *x;
    cudaGetSymbolAddress((void**)&src16, g_src16);
    cudaGetSymbolAddress((void**)&q16,  g_q16);
    cudaGetSymbolAddress((void**)&k16,  g_k16);
    cudaGetSymbolAddress((void**)&v16,  g_v16);
    cudaGetSymbolAddress((void**)&ao16, g_ao16);
    cudaGetSymbolAddress((void**)&x16,  g_x16);
    cudaGetSymbolAddress((void**)&ff16, g_ff16);
    cudaGetSymbolAddress((void**)&wt,   g_wt16);
    cudaGetSymbolAddress((void**)&t,    g_t);
    cudaGetSymbolAddress((void**)&x,    g_x);

    cudaFuncSetAttribute(qkv_kernel,     cudaFuncAttributeMaxDynamicSharedMemorySize, SMEM_GEMM);
    cudaFuncSetAttribute(gemm_kernel<1>, cudaFuncAttributeMaxDynamicSharedMemorySize, SMEM_GEMM);
    cudaFuncSetAttribute(gemm_kernel<2>, cudaFuncAttributeMaxDynamicSharedMemorySize, SMEM_GEMM);
    cudaFuncSetAttribute(attn_kernel,    cudaFuncAttributeMaxDynamicSharedMemorySize, SMEM_ATTN);

    // ---- prep: src->fp16, weights transpose+fp16 ----
    cvt16_kernel<<<(NT*DD/4 + 255)/256, 256>>>(src, src16, NT*DD/4);
    dim3 tb(32, 8);
    transpose4_kernel<<<dim3(DD/32, DD/32, 4), tb>>>(Wq, Wk, Wv, Wo, wt);
    transpose16_kernel<<<dim3(DFF/32, DD/32), tb>>>(W1, wt + WT_1, DD, DFF);
    transpose16_kernel<<<dim3(DD/32, DFF/32), tb>>>(W2, wt + WT_2, DFF, DD);

    dim3 gqkv(DD / 128, NT / 128, 3);
    dim3 g512(DD / 128, NT / 128);
    dim3 gff (DFF / 128, NT / 128);

    qkv_kernel<<<gqkv, 256, SMEM_GEMM>>>(src16, wt, bq, bk, bv, q16, k16, v16);
    attn_kernel<<<BB * HH, 256, SMEM_ATTN>>>(q16, k16, v16, mat, scores_out, ao16);
    gemm_kernel<2><<<g512, 256, SMEM_GEMM>>>(ao16, wt + WT_O, bo, src, t, DD, DD);
    ln_kernel<<<NT / 8, 256>>>(t, ln1g, ln1b, x, x16);
    gemm_kernel<1><<<gff, 256, SMEM_GEMM>>>(x16, wt + WT_1, b1, nullptr, ff16, DFF, DD);
    gemm_kernel<2><<<g512, 256, SMEM_GEMM>>>(ff16, wt + WT_2, b2, x, t, DD, DFF);
    ln_kernel<<<NT / 8, 256>>>(t, ln2g, ln2b, y_out, nullptr);
}